// round 1
// baseline (speedup 1.0000x reference)
#include <cuda_runtime.h>
#include <math.h>

#define D_MODEL 1024
#define NHEAD 16
#define HEAD_DIM 64
#define BATCH 2
#define SEQ 2048
#define MTOT (BATCH * SEQ) /* 4096 */

// ---------------------------------------------------------------------------
// Scratch (device globals — no allocation allowed anywhere)
// ---------------------------------------------------------------------------
__device__ float g_q[MTOT * D_MODEL];
__device__ float g_k[MTOT * D_MODEL];
__device__ float g_v[MTOT * D_MODEL];
__device__ float g_attn[MTOT * D_MODEL];

// ---------------------------------------------------------------------------
// GEMM:  C[m,n] = sum_k A[m,k] * W[n,k] + bias[n]   (W stored row-major [N,K])
// optional SFN epilogue: c = clip(rint(c*2), -8, 8) * 0.5
// Tile: 128x128x16, 256 threads, 8x8 per-thread microtile.
// ---------------------------------------------------------------------------
#define GBM 128
#define GBN 128
#define GBK 16

__global__ __launch_bounds__(256) void gemm_bias_act(
    const float* __restrict__ A, const float* __restrict__ W,
    const float* __restrict__ bias, float* __restrict__ C,
    int Kdim, int Ncols, int apply_sfn)
{
    __shared__ float As[GBK][GBM + 4];
    __shared__ float Ws[GBK][GBN + 4];

    const int tid = threadIdx.x;
    const int bm = blockIdx.y * GBM;
    const int bn = blockIdx.x * GBN;
    const int tx = tid & 15;   // col group
    const int ty = tid >> 4;   // row group

    const int lr = tid >> 2;         // 0..63 loader row
    const int lc = (tid & 3) << 2;   // 0,4,8,12 loader col (float4)

    const float* Ap0 = A + (size_t)(bm + lr) * Kdim + lc;
    const float* Ap1 = A + (size_t)(bm + lr + 64) * Kdim + lc;
    const float* Wp0 = W + (size_t)(bn + lr) * Kdim + lc;
    const float* Wp1 = W + (size_t)(bn + lr + 64) * Kdim + lc;

    float acc[8][8];
#pragma unroll
    for (int i = 0; i < 8; i++)
#pragma unroll
        for (int j = 0; j < 8; j++) acc[i][j] = 0.f;

    for (int k0 = 0; k0 < Kdim; k0 += GBK) {
        float4 a0 = *(const float4*)(Ap0 + k0);
        float4 a1 = *(const float4*)(Ap1 + k0);
        float4 w0 = *(const float4*)(Wp0 + k0);
        float4 w1 = *(const float4*)(Wp1 + k0);

        __syncthreads();
        As[lc + 0][lr] = a0.x;  As[lc + 1][lr] = a0.y;
        As[lc + 2][lr] = a0.z;  As[lc + 3][lr] = a0.w;
        As[lc + 0][lr + 64] = a1.x;  As[lc + 1][lr + 64] = a1.y;
        As[lc + 2][lr + 64] = a1.z;  As[lc + 3][lr + 64] = a1.w;
        Ws[lc + 0][lr] = w0.x;  Ws[lc + 1][lr] = w0.y;
        Ws[lc + 2][lr] = w0.z;  Ws[lc + 3][lr] = w0.w;
        Ws[lc + 0][lr + 64] = w1.x;  Ws[lc + 1][lr + 64] = w1.y;
        Ws[lc + 2][lr + 64] = w1.z;  Ws[lc + 3][lr + 64] = w1.w;
        __syncthreads();

#pragma unroll
        for (int kk = 0; kk < GBK; kk++) {
            float af[8], wf[8];
            *(float4*)&af[0] = *(const float4*)&As[kk][ty * 8];
            *(float4*)&af[4] = *(const float4*)&As[kk][ty * 8 + 4];
            *(float4*)&wf[0] = *(const float4*)&Ws[kk][tx * 8];
            *(float4*)&wf[4] = *(const float4*)&Ws[kk][tx * 8 + 4];
#pragma unroll
            for (int i = 0; i < 8; i++)
#pragma unroll
                for (int j = 0; j < 8; j++)
                    acc[i][j] = fmaf(af[i], wf[j], acc[i][j]);
        }
    }

#pragma unroll
    for (int i = 0; i < 8; i++) {
        const int m = bm + ty * 8 + i;
        float4 o0, o1;
        float* po = (float*)&o0;
#pragma unroll
        for (int j = 0; j < 8; j++) {
            const int n = bn + tx * 8 + j;
            float c = acc[i][j] + bias[n];
            if (apply_sfn) {
                float r = rintf(c * 2.0f);            // round-half-even like jnp.round
                r = fminf(8.0f, fmaxf(-8.0f, r));     // clip to +/- SF_LEVELS
                c = r * 0.5f;
            }
            if (j < 4) ((float*)&o0)[j] = c; else ((float*)&o1)[j - 4] = c;
        }
        (void)po;
        *(float4*)(C + (size_t)m * Ncols + bn + tx * 8)     = o0;
        *(float4*)(C + (size_t)m * Ncols + bn + tx * 8 + 4) = o1;
    }
}

// ---------------------------------------------------------------------------
// qk-norm: per (b,l,h) row of 64 elems: x / sqrt(mean(x^2)+eps) * g
// Layout: row r = m*NHEAD + h is contiguous 64 floats at base + r*64.
// One warp per row, both Q and K handled together.
// ---------------------------------------------------------------------------
__global__ void qknorm_kernel(float* __restrict__ Q, float* __restrict__ K,
                              const float* __restrict__ gq,
                              const float* __restrict__ gk)
{
    const int row  = blockIdx.x * blockDim.y + threadIdx.y;
    const int lane = threadIdx.x;

    float* qb = Q + (size_t)row * 64;
    float* kb = K + (size_t)row * 64;

    float2 xq = *(float2*)(qb + lane * 2);
    float2 xk = *(float2*)(kb + lane * 2);

    float sq = xq.x * xq.x + xq.y * xq.y;
    float sk = xk.x * xk.x + xk.y * xk.y;
#pragma unroll
    for (int o = 16; o; o >>= 1) {
        sq += __shfl_xor_sync(0xffffffffu, sq, o);
        sk += __shfl_xor_sync(0xffffffffu, sk, o);
    }
    const float invq = rsqrtf(sq * (1.0f / 64.0f) + 1e-6f);
    const float invk = rsqrtf(sk * (1.0f / 64.0f) + 1e-6f);

    const float gq0 = gq[lane * 2], gq1 = gq[lane * 2 + 1];
    const float gk0 = gk[lane * 2], gk1 = gk[lane * 2 + 1];

    xq.x = xq.x * invq * gq0;  xq.y = xq.y * invq * gq1;
    xk.x = xk.x * invk * gk0;  xk.y = xk.y * invk * gk1;

    *(float2*)(qb + lane * 2) = xq;
    *(float2*)(kb + lane * 2) = xk;
}

// ---------------------------------------------------------------------------
// Flash attention (fp32, non-causal): one query per thread, 128 queries/block.
// K/V tiles of 64 keys in padded smem, online softmax in 32-key chunks.
// Output written directly in [B, L, H*Dh] layout.
// ---------------------------------------------------------------------------
#define FBM 128
#define FBN 64

__global__ __launch_bounds__(128) void flash_attn(
    const float* __restrict__ Qg, const float* __restrict__ Kg,
    const float* __restrict__ Vg, float* __restrict__ Og)
{
    __shared__ float Ks[FBN][68];
    __shared__ float Vs[FBN][68];

    const int t  = threadIdx.x;
    const int bh = blockIdx.y;
    const int b  = bh >> 4;
    const int h  = bh & 15;
    const int l  = blockIdx.x * FBM + t;

    const float scale = 0.125f;  // 64^-0.5

    // load this thread's (normalized) query, pre-scaled
    float q[64];
    {
        const float* qp = Qg + ((size_t)(b * SEQ + l)) * D_MODEL + h * HEAD_DIM;
#pragma unroll
        for (int i = 0; i < 16; i++) {
            float4 v4 = *(const float4*)(qp + i * 4);
            q[i * 4 + 0] = v4.x * scale;  q[i * 4 + 1] = v4.y * scale;
            q[i * 4 + 2] = v4.z * scale;  q[i * 4 + 3] = v4.w * scale;
        }
    }

    float m_i = -INFINITY, l_i = 0.0f;
    float acc[64];
#pragma unroll
    for (int d = 0; d < 64; d++) acc[d] = 0.0f;

    const int kr = t >> 1;           // 0..63  (key row within tile)
    const int kh = (t & 1) * 32;     // half-row offset

    for (int kt = 0; kt < SEQ; kt += FBN) {
        const float* kgp = Kg + ((size_t)(b * SEQ + kt + kr)) * D_MODEL + h * HEAD_DIM + kh;
        const float* vgp = Vg + ((size_t)(b * SEQ + kt + kr)) * D_MODEL + h * HEAD_DIM + kh;

        __syncthreads();
#pragma unroll
        for (int i = 0; i < 8; i++) {
            *(float4*)&Ks[kr][kh + i * 4] = *(const float4*)(kgp + i * 4);
            *(float4*)&Vs[kr][kh + i * 4] = *(const float4*)(vgp + i * 4);
        }
        __syncthreads();

        for (int c = 0; c < 2; c++) {            // two 32-key softmax chunks
            float s[32];
            float mnew = m_i;
#pragma unroll
            for (int j = 0; j < 32; j++) {
                const int jj = c * 32 + j;
                float s0 = 0.f, s1 = 0.f, s2 = 0.f, s3 = 0.f;
#pragma unroll
                for (int d = 0; d < 64; d += 4) {
                    float4 k4 = *(const float4*)&Ks[jj][d];
                    s0 = fmaf(q[d + 0], k4.x, s0);
                    s1 = fmaf(q[d + 1], k4.y, s1);
                    s2 = fmaf(q[d + 2], k4.z, s2);
                    s3 = fmaf(q[d + 3], k4.w, s3);
                }
                s[j] = (s0 + s1) + (s2 + s3);
                mnew = fmaxf(mnew, s[j]);
            }
            const float corr = __expf(m_i - mnew);
            m_i = mnew;
            l_i *= corr;
#pragma unroll
            for (int d = 0; d < 64; d++) acc[d] *= corr;

#pragma unroll
            for (int j = 0; j < 32; j++) {
                const int jj = c * 32 + j;
                const float p = __expf(s[j] - mnew);
                l_i += p;
#pragma unroll
                for (int d = 0; d < 64; d += 4) {
                    float4 v4 = *(const float4*)&Vs[jj][d];
                    acc[d + 0] = fmaf(p, v4.x, acc[d + 0]);
                    acc[d + 1] = fmaf(p, v4.y, acc[d + 1]);
                    acc[d + 2] = fmaf(p, v4.z, acc[d + 2]);
                    acc[d + 3] = fmaf(p, v4.w, acc[d + 3]);
                }
            }
        }
    }

    const float inv = 1.0f / l_i;
    float* op = Og + ((size_t)(b * SEQ + l)) * D_MODEL + h * HEAD_DIM;
#pragma unroll
    for (int d = 0; d < 64; d += 4) {
        float4 o4;
        o4.x = acc[d + 0] * inv;  o4.y = acc[d + 1] * inv;
        o4.z = acc[d + 2] * inv;  o4.w = acc[d + 3] * inv;
        *(float4*)(op + d) = o4;
    }
}

// ---------------------------------------------------------------------------
// Launcher
// ---------------------------------------------------------------------------
extern "C" void kernel_launch(void* const* d_in, const int* in_sizes, int n_in,
                              void* d_out, int out_size)
{
    (void)in_sizes; (void)n_in; (void)out_size;
    const float* x  = (const float*)d_in[0];
    const float* Wq = (const float*)d_in[1];
    const float* bq = (const float*)d_in[2];
    const float* Wk = (const float*)d_in[3];
    const float* bk = (const float*)d_in[4];
    const float* Wv = (const float*)d_in[5];
    const float* bv = (const float*)d_in[6];
    const float* Wo = (const float*)d_in[7];
    const float* bo = (const float*)d_in[8];
    const float* gq = (const float*)d_in[9];
    const float* gk = (const float*)d_in[10];
    float* out = (float*)d_out;

    float *qp, *kp, *vp, *ap;
    cudaGetSymbolAddress((void**)&qp, g_q);
    cudaGetSymbolAddress((void**)&kp, g_k);
    cudaGetSymbolAddress((void**)&vp, g_v);
    cudaGetSymbolAddress((void**)&ap, g_attn);

    dim3 ggrid(D_MODEL / GBN, MTOT / GBM);

    gemm_bias_act<<<ggrid, 256>>>(x, Wq, bq, qp, D_MODEL, D_MODEL, 1);
    gemm_bias_act<<<ggrid, 256>>>(x, Wk, bk, kp, D_MODEL, D_MODEL, 1);
    gemm_bias_act<<<ggrid, 256>>>(x, Wv, bv, vp, D_MODEL, D_MODEL, 1);

    {
        dim3 nb(32, 8);
        int nrows = MTOT * NHEAD;          // 65536 rows of 64
        qknorm_kernel<<<nrows / 8, nb>>>(qp, kp, gq, gk);
    }

    {
        dim3 fgrid(SEQ / FBM, BATCH * NHEAD);
        flash_attn<<<fgrid, 128>>>(qp, kp, vp, ap);
    }

    gemm_bias_act<<<ggrid, 256>>>(ap, Wo, bo, out, D_MODEL, D_MODEL, 0);
}

// round 5
// speedup vs baseline: 2.0367x; 2.0367x over previous
#include <cuda_runtime.h>
#include <cuda_bf16.h>
#include <math.h>
#include <stdint.h>

#define D_MODEL 1024
#define NHEAD 16
#define HEAD_DIM 64
#define BATCH 2
#define SEQ 2048
#define MTOT (BATCH * SEQ) /* 4096 */

// ---------------------------------------------------------------------------
// Scratch (device globals — no allocation allowed anywhere)
// ---------------------------------------------------------------------------
__device__ float g_q[MTOT * D_MODEL];
__device__ float g_k[MTOT * D_MODEL];
__device__ float g_v[MTOT * D_MODEL];
__device__ float g_attn[MTOT * D_MODEL];
__device__ __nv_bfloat16 g_xh[MTOT * D_MODEL];
__device__ __nv_bfloat16 g_xm[MTOT * D_MODEL];
__device__ __nv_bfloat16 g_wh[D_MODEL * D_MODEL];
__device__ __nv_bfloat16 g_wm[D_MODEL * D_MODEL];

// ---------------------------------------------------------------------------
// helpers
// ---------------------------------------------------------------------------
__device__ __forceinline__ uint32_t smem_u32(const void* p) {
    uint32_t a;
    asm("{ .reg .u64 t; cvta.to.shared.u64 t, %1; cvt.u32.u64 %0, t; }" : "=r"(a) : "l"(p));
    return a;
}
__device__ __forceinline__ void cp_async16(uint32_t sa, const void* ga) {
    asm volatile("cp.async.cg.shared.global [%0], [%1], 16;" :: "r"(sa), "l"(ga) : "memory");
}
#define CP_COMMIT() asm volatile("cp.async.commit_group;" ::: "memory")
#define CP_WAIT1()  asm volatile("cp.async.wait_group 1;" ::: "memory")

__device__ __forceinline__ void ldm_x4(uint32_t& r0, uint32_t& r1, uint32_t& r2, uint32_t& r3,
                                       uint32_t addr) {
    asm volatile("ldmatrix.sync.aligned.m8n8.x4.shared.b16 {%0,%1,%2,%3}, [%4];"
                 : "=r"(r0), "=r"(r1), "=r"(r2), "=r"(r3) : "r"(addr));
}
__device__ __forceinline__ void ldm_x4t(uint32_t& r0, uint32_t& r1, uint32_t& r2, uint32_t& r3,
                                        uint32_t addr) {
    asm volatile("ldmatrix.sync.aligned.m8n8.x4.trans.shared.b16 {%0,%1,%2,%3}, [%4];"
                 : "=r"(r0), "=r"(r1), "=r"(r2), "=r"(r3) : "r"(addr));
}
__device__ __forceinline__ void mma_bf16(float* c, const uint32_t* a, const uint32_t* b) {
    asm volatile(
        "mma.sync.aligned.m16n8k16.row.col.f32.bf16.bf16.f32 "
        "{%0,%1,%2,%3}, {%4,%5,%6,%7}, {%8,%9}, {%0,%1,%2,%3};"
        : "+f"(c[0]), "+f"(c[1]), "+f"(c[2]), "+f"(c[3])
        : "r"(a[0]), "r"(a[1]), "r"(a[2]), "r"(a[3]), "r"(b[0]), "r"(b[1]));
}

// ---------------------------------------------------------------------------
// QKV GEMM: fp32 SIMT (SFN-guarded ops need fp32-class accumulation)
// ---------------------------------------------------------------------------
#define GBM 128
#define GBN 128
#define GBK 16

__global__ __launch_bounds__(256) void gemm_bias_act(
    const float* __restrict__ A, const float* __restrict__ W,
    const float* __restrict__ bias, float* __restrict__ C,
    int Kdim, int Ncols, int apply_sfn)
{
    __shared__ float As[GBK][GBM + 4];
    __shared__ float Ws[GBK][GBN + 4];

    const int tid = threadIdx.x;
    const int bm = blockIdx.y * GBM;
    const int bn = blockIdx.x * GBN;
    const int tx = tid & 15;
    const int ty = tid >> 4;

    const int lr = tid >> 2;
    const int lc = (tid & 3) << 2;

    const float* Ap0 = A + (size_t)(bm + lr) * Kdim + lc;
    const float* Ap1 = A + (size_t)(bm + lr + 64) * Kdim + lc;
    const float* Wp0 = W + (size_t)(bn + lr) * Kdim + lc;
    const float* Wp1 = W + (size_t)(bn + lr + 64) * Kdim + lc;

    float acc[8][8];
#pragma unroll
    for (int i = 0; i < 8; i++)
#pragma unroll
        for (int j = 0; j < 8; j++) acc[i][j] = 0.f;

    for (int k0 = 0; k0 < Kdim; k0 += GBK) {
        float4 a0 = *(const float4*)(Ap0 + k0);
        float4 a1 = *(const float4*)(Ap1 + k0);
        float4 w0 = *(const float4*)(Wp0 + k0);
        float4 w1 = *(const float4*)(Wp1 + k0);

        __syncthreads();
        As[lc + 0][lr] = a0.x;  As[lc + 1][lr] = a0.y;
        As[lc + 2][lr] = a0.z;  As[lc + 3][lr] = a0.w;
        As[lc + 0][lr + 64] = a1.x;  As[lc + 1][lr + 64] = a1.y;
        As[lc + 2][lr + 64] = a1.z;  As[lc + 3][lr + 64] = a1.w;
        Ws[lc + 0][lr] = w0.x;  Ws[lc + 1][lr] = w0.y;
        Ws[lc + 2][lr] = w0.z;  Ws[lc + 3][lr] = w0.w;
        Ws[lc + 0][lr + 64] = w1.x;  Ws[lc + 1][lr + 64] = w1.y;
        Ws[lc + 2][lr + 64] = w1.z;  Ws[lc + 3][lr + 64] = w1.w;
        __syncthreads();

#pragma unroll
        for (int kk = 0; kk < GBK; kk++) {
            float af[8], wf[8];
            *(float4*)&af[0] = *(const float4*)&As[kk][ty * 8];
            *(float4*)&af[4] = *(const float4*)&As[kk][ty * 8 + 4];
            *(float4*)&wf[0] = *(const float4*)&Ws[kk][tx * 8];
            *(float4*)&wf[4] = *(const float4*)&Ws[kk][tx * 8 + 4];
#pragma unroll
            for (int i = 0; i < 8; i++)
#pragma unroll
                for (int j = 0; j < 8; j++)
                    acc[i][j] = fmaf(af[i], wf[j], acc[i][j]);
        }
    }

#pragma unroll
    for (int i = 0; i < 8; i++) {
        const int m = bm + ty * 8 + i;
        float4 o0, o1;
#pragma unroll
        for (int j = 0; j < 8; j++) {
            const int n = bn + tx * 8 + j;
            float c = acc[i][j] + bias[n];
            if (apply_sfn) {
                float r = rintf(c * 2.0f);
                r = fminf(8.0f, fmaxf(-8.0f, r));
                c = r * 0.5f;
            }
            if (j < 4) ((float*)&o0)[j] = c; else ((float*)&o1)[j - 4] = c;
        }
        *(float4*)(C + (size_t)m * Ncols + bn + tx * 8)     = o0;
        *(float4*)(C + (size_t)m * Ncols + bn + tx * 8 + 4) = o1;
    }
}

// ---------------------------------------------------------------------------
// qk-norm
// ---------------------------------------------------------------------------
__global__ void qknorm_kernel(float* __restrict__ Q, float* __restrict__ K,
                              const float* __restrict__ gq,
                              const float* __restrict__ gk)
{
    const int row  = blockIdx.x * blockDim.y + threadIdx.y;
    const int lane = threadIdx.x;

    float* qb = Q + (size_t)row * 64;
    float* kb = K + (size_t)row * 64;

    float2 xq = *(float2*)(qb + lane * 2);
    float2 xk = *(float2*)(kb + lane * 2);

    float sq = xq.x * xq.x + xq.y * xq.y;
    float sk = xk.x * xk.x + xk.y * xk.y;
#pragma unroll
    for (int o = 16; o; o >>= 1) {
        sq += __shfl_xor_sync(0xffffffffu, sq, o);
        sk += __shfl_xor_sync(0xffffffffu, sk, o);
    }
    const float invq = rsqrtf(sq * (1.0f / 64.0f) + 1e-6f);
    const float invk = rsqrtf(sk * (1.0f / 64.0f) + 1e-6f);

    const float gq0 = gq[lane * 2], gq1 = gq[lane * 2 + 1];
    const float gk0 = gk[lane * 2], gk1 = gk[lane * 2 + 1];

    xq.x = xq.x * invq * gq0;  xq.y = xq.y * invq * gq1;
    xk.x = xk.x * invk * gk0;  xk.y = xk.y * invk * gk1;

    *(float2*)(qb + lane * 2) = xq;
    *(float2*)(kb + lane * 2) = xk;
}

// ---------------------------------------------------------------------------
// Flash attention via mma.sync bf16.
// Q,K: 2-way bf16 split (products hh, lh, hm). V: exact bf16. P: 2-way split.
// Block: 256 thr (8 warps), 128 queries (16 per warp), KV tiles of 64.
// FIX vs round 4: K-tile ldmatrix uses B-operand addressing (l4 -> n-row half,
// l3 -> k half), matching the proven gemm_mma2 layout.
// ---------------------------------------------------------------------------
#define AT_ROWB 144   /* bytes per 64-bf16 row (+16B pad: conflict-free ldmatrix) */
#define FA_SMEM (2 * 128 * AT_ROWB)  /* Q staging (Qh+Ql) = 36864; > KV 27648 */

__global__ __launch_bounds__(256, 1) void flash_mma(
    const float* __restrict__ Qg, const float* __restrict__ Kg,
    const float* __restrict__ Vg, float* __restrict__ Og)
{
    extern __shared__ char smp[];
    const uint32_t sb = smem_u32(smp);
    // overlay: phase 1: Qh[128][144], Ql[128][144]; phase 2: Kh/Km/V [64][144] each
    const int oQh = 0, oQl = 128 * AT_ROWB;
    const int oKh = 0, oKm = 64 * AT_ROWB, oV = 128 * AT_ROWB;

    const int tid = threadIdx.x, wid = tid >> 5, lane = tid & 31;
    const int b = blockIdx.y >> 4, h = blockIdx.y & 15;
    const int q0 = blockIdx.x * 128;

    const int lr = lane & 7, l3 = (lane >> 3) & 1, l4 = (lane >> 4) & 1;

    // ---- stage Q (x0.125 exact; 2-way bf16 split) ----
    {
        const int row = tid >> 1;
        const int cb = (tid & 1) * 32;
        const float* qp = Qg + ((size_t)(b * SEQ + q0 + row)) * D_MODEL + h * HEAD_DIM + cb;
        char* dh_ = smp + oQh + row * AT_ROWB + cb * 2;
        char* dl_ = smp + oQl + row * AT_ROWB + cb * 2;
#pragma unroll
        for (int i = 0; i < 8; i++) {
            float4 f = *(const float4*)(qp + i * 4);
            f.x *= 0.125f; f.y *= 0.125f; f.z *= 0.125f; f.w *= 0.125f;
            __nv_bfloat162 h01 = __floats2bfloat162_rn(f.x, f.y);
            __nv_bfloat162 h23 = __floats2bfloat162_rn(f.z, f.w);
            __nv_bfloat162 l01 = __floats2bfloat162_rn(f.x - __bfloat162float(h01.x),
                                                       f.y - __bfloat162float(h01.y));
            __nv_bfloat162 l23 = __floats2bfloat162_rn(f.z - __bfloat162float(h23.x),
                                                       f.w - __bfloat162float(h23.y));
            *(__nv_bfloat162*)(dh_ + i * 8)     = h01;
            *(__nv_bfloat162*)(dh_ + i * 8 + 4) = h23;
            *(__nv_bfloat162*)(dl_ + i * 8)     = l01;
            *(__nv_bfloat162*)(dl_ + i * 8 + 4) = l23;
        }
    }
    __syncthreads();

    // ---- Q fragments to registers (A-operand addressing: l3 rows, l4 k) ----
    uint32_t qh[4][4], ql[4][4];
    {
        const int rbase = wid * 16 + lr + l3 * 8;
#pragma unroll
        for (int ks = 0; ks < 4; ks++) {
            ldm_x4(qh[ks][0], qh[ks][1], qh[ks][2], qh[ks][3],
                   sb + oQh + rbase * AT_ROWB + ks * 32 + l4 * 16);
            ldm_x4(ql[ks][0], ql[ks][1], ql[ks][2], ql[ks][3],
                   sb + oQl + rbase * AT_ROWB + ks * 32 + l4 * 16);
        }
    }
    __syncthreads();

    float m_lo = -INFINITY, m_hi = -INFINITY, l_lo = 0.f, l_hi = 0.f;
    float acc[8][4];
#pragma unroll
    for (int i = 0; i < 8; i++)
#pragma unroll
        for (int j = 0; j < 4; j++) acc[i][j] = 0.f;

    for (int kt = 0; kt < SEQ / 64; kt++) {
        // ---- stage K (split) + V (exact bf16) ----
        {
            const int row = tid >> 2;
            const int cb = (tid & 3) * 16;
            const float* kp = Kg + ((size_t)(b * SEQ + kt * 64 + row)) * D_MODEL + h * HEAD_DIM + cb;
            const float* vp = Vg + ((size_t)(b * SEQ + kt * 64 + row)) * D_MODEL + h * HEAD_DIM + cb;
            char* dkh = smp + oKh + row * AT_ROWB + cb * 2;
            char* dkm = smp + oKm + row * AT_ROWB + cb * 2;
            char* dv  = smp + oV  + row * AT_ROWB + cb * 2;
#pragma unroll
            for (int i = 0; i < 4; i++) {
                float4 kf = *(const float4*)(kp + i * 4);
                __nv_bfloat162 kh01 = __floats2bfloat162_rn(kf.x, kf.y);
                __nv_bfloat162 kh23 = __floats2bfloat162_rn(kf.z, kf.w);
                __nv_bfloat162 km01 = __floats2bfloat162_rn(kf.x - __bfloat162float(kh01.x),
                                                            kf.y - __bfloat162float(kh01.y));
                __nv_bfloat162 km23 = __floats2bfloat162_rn(kf.z - __bfloat162float(kh23.x),
                                                            kf.w - __bfloat162float(kh23.y));
                *(__nv_bfloat162*)(dkh + i * 8)     = kh01;
                *(__nv_bfloat162*)(dkh + i * 8 + 4) = kh23;
                *(__nv_bfloat162*)(dkm + i * 8)     = km01;
                *(__nv_bfloat162*)(dkm + i * 8 + 4) = km23;
                float4 vf = *(const float4*)(vp + i * 4);
                *(__nv_bfloat162*)(dv + i * 8)     = __floats2bfloat162_rn(vf.x, vf.y);
                *(__nv_bfloat162*)(dv + i * 8 + 4) = __floats2bfloat162_rn(vf.z, vf.w);
            }
        }
        __syncthreads();

        // ---- S = Qs·K^T (3 products); B-operand addressing: l4 rows, l3 k ----
        float s[8][4];
#pragma unroll
        for (int i = 0; i < 8; i++)
#pragma unroll
            for (int j = 0; j < 4; j++) s[i][j] = 0.f;

#pragma unroll
        for (int np = 0; np < 4; np++) {
            const int rb = np * 16 + lr + l4 * 8;           // FIX: l4 selects n-row half
#pragma unroll
            for (int ks = 0; ks < 4; ks++) {
                uint32_t bh0, bh1, bh2, bh3, bm0, bm1, bm2, bm3;
                ldm_x4(bh0, bh1, bh2, bh3, sb + oKh + rb * AT_ROWB + ks * 32 + l3 * 16);  // FIX: l3 k-half
                ldm_x4(bm0, bm1, bm2, bm3, sb + oKm + rb * AT_ROWB + ks * 32 + l3 * 16);
                uint32_t b0[2] = {bh0, bh1}, b1[2] = {bh2, bh3};   // {klo,khi} per n-group
                uint32_t c0[2] = {bm0, bm1}, c1[2] = {bm2, bm3};
                mma_bf16(s[np * 2 + 0], qh[ks], b0);
                mma_bf16(s[np * 2 + 0], ql[ks], b0);
                mma_bf16(s[np * 2 + 0], qh[ks], c0);
                mma_bf16(s[np * 2 + 1], qh[ks], b1);
                mma_bf16(s[np * 2 + 1], ql[ks], b1);
                mma_bf16(s[np * 2 + 1], qh[ks], c1);
            }
        }

        // ---- online softmax (row stats over lane quads) ----
        float mx_lo = m_lo, mx_hi = m_hi;
#pragma unroll
        for (int i = 0; i < 8; i++) {
            mx_lo = fmaxf(mx_lo, fmaxf(s[i][0], s[i][1]));
            mx_hi = fmaxf(mx_hi, fmaxf(s[i][2], s[i][3]));
        }
        mx_lo = fmaxf(mx_lo, __shfl_xor_sync(0xffffffffu, mx_lo, 1));
        mx_lo = fmaxf(mx_lo, __shfl_xor_sync(0xffffffffu, mx_lo, 2));
        mx_hi = fmaxf(mx_hi, __shfl_xor_sync(0xffffffffu, mx_hi, 1));
        mx_hi = fmaxf(mx_hi, __shfl_xor_sync(0xffffffffu, mx_hi, 2));

        const float corr_lo = __expf(m_lo - mx_lo);
        const float corr_hi = __expf(m_hi - mx_hi);
        m_lo = mx_lo; m_hi = mx_hi;
        l_lo *= corr_lo; l_hi *= corr_hi;
#pragma unroll
        for (int i = 0; i < 8; i++) {
            acc[i][0] *= corr_lo; acc[i][1] *= corr_lo;
            acc[i][2] *= corr_hi; acc[i][3] *= corr_hi;
        }

        uint32_t ph[4][4], pm[4][4];
#pragma unroll
        for (int t = 0; t < 4; t++) {
#pragma unroll
            for (int half = 0; half < 2; half++) {     // key sub-tiles 2t, 2t+1
                const int nt = 2 * t + half;
                float p0 = __expf(s[nt][0] - mx_lo);
                float p1 = __expf(s[nt][1] - mx_lo);
                float p2 = __expf(s[nt][2] - mx_hi);
                float p3 = __expf(s[nt][3] - mx_hi);
                l_lo += p0 + p1; l_hi += p2 + p3;
                __nv_bfloat162 h01 = __floats2bfloat162_rn(p0, p1);
                __nv_bfloat162 h23 = __floats2bfloat162_rn(p2, p3);
                __nv_bfloat162 m01 = __floats2bfloat162_rn(p0 - __bfloat162float(h01.x),
                                                           p1 - __bfloat162float(h01.y));
                __nv_bfloat162 m23 = __floats2bfloat162_rn(p2 - __bfloat162float(h23.x),
                                                           p3 - __bfloat162float(h23.y));
                ph[t][half * 2 + 0] = *(uint32_t*)&h01;   // a0/a2: (row,   k half)
                ph[t][half * 2 + 1] = *(uint32_t*)&h23;   // a1/a3: (row+8, k half)
                pm[t][half * 2 + 0] = *(uint32_t*)&m01;
                pm[t][half * 2 + 1] = *(uint32_t*)&m23;
            }
        }

        // ---- acc += P·V (2 products), V via ldmatrix.trans ----
#pragma unroll
        for (int np = 0; np < 4; np++) {
#pragma unroll
            for (int t = 0; t < 4; t++) {
                uint32_t v0, v1, v2, v3;
                ldm_x4t(v0, v1, v2, v3,
                        sb + oV + (t * 16 + lr + l3 * 8) * AT_ROWB + np * 32 + l4 * 16);
                uint32_t b0[2] = {v0, v1}, b1[2] = {v2, v3};   // {key-lo,key-hi} per head-grp
                mma_bf16(acc[np * 2 + 0], ph[t], b0);
                mma_bf16(acc[np * 2 + 0], pm[t], b0);
                mma_bf16(acc[np * 2 + 1], ph[t], b1);
                mma_bf16(acc[np * 2 + 1], pm[t], b1);
            }
        }
        __syncthreads();
    }

    // ---- finalize ----
    l_lo += __shfl_xor_sync(0xffffffffu, l_lo, 1);
    l_lo += __shfl_xor_sync(0xffffffffu, l_lo, 2);
    l_hi += __shfl_xor_sync(0xffffffffu, l_hi, 1);
    l_hi += __shfl_xor_sync(0xffffffffu, l_hi, 2);
    const float inv_lo = 1.0f / l_lo;
    const float inv_hi = 1.0f / l_hi;

    const int r_lo = q0 + wid * 16 + (lane >> 2);
    const int r_hi = r_lo + 8;
    float* o_lo = Og + ((size_t)(b * SEQ + r_lo)) * D_MODEL + h * HEAD_DIM + (lane & 3) * 2;
    float* o_hi = Og + ((size_t)(b * SEQ + r_hi)) * D_MODEL + h * HEAD_DIM + (lane & 3) * 2;
#pragma unroll
    for (int nt = 0; nt < 8; nt++) {
        *(float2*)(o_lo + nt * 8) = make_float2(acc[nt][0] * inv_lo, acc[nt][1] * inv_lo);
        *(float2*)(o_hi + nt * 8) = make_float2(acc[nt][2] * inv_hi, acc[nt][3] * inv_hi);
    }
}

// ---------------------------------------------------------------------------
// split fp32 -> 2x bf16 (hi, mid)
// ---------------------------------------------------------------------------
__global__ void split2(const float4* __restrict__ src, uint2* __restrict__ H,
                       uint2* __restrict__ M, int n4)
{
    int i = blockIdx.x * blockDim.x + threadIdx.x;
    if (i >= n4) return;
    float4 x = src[i];
    float xs[4] = {x.x, x.y, x.z, x.w};
    uint16_t h[4], m[4];
#pragma unroll
    for (int j = 0; j < 4; j++) {
        __nv_bfloat16 hb = __float2bfloat16(xs[j]);
        float r1 = xs[j] - __bfloat162float(hb);
        __nv_bfloat16 mb = __float2bfloat16(r1);
        h[j] = __bfloat16_as_ushort(hb);
        m[j] = __bfloat16_as_ushort(mb);
    }
    H[i] = make_uint2((uint32_t)h[0] | ((uint32_t)h[1] << 16), (uint32_t)h[2] | ((uint32_t)h[3] << 16));
    M[i] = make_uint2((uint32_t)m[0] | ((uint32_t)m[1] << 16), (uint32_t)m[2] | ((uint32_t)m[3] << 16));
}

// ---------------------------------------------------------------------------
// Wo GEMM via mma.sync, 2-way split (hh, hm, mh):  C = A·W^T + bias
// ---------------------------------------------------------------------------
#define BM 128
#define BN 128
#define BK 32
#define ROWB 80
#define MATB (128 * ROWB)
#define STAGEB (4 * MATB)
#define GEMM_SMEM (2 * STAGEB)

__global__ __launch_bounds__(256, 1) void gemm_mma2(
    const __nv_bfloat16* __restrict__ Ah, const __nv_bfloat16* __restrict__ Am,
    const __nv_bfloat16* __restrict__ Wh, const __nv_bfloat16* __restrict__ Wm,
    const float* __restrict__ bias, float* __restrict__ C)
{
    extern __shared__ char dsm[];
    const uint32_t sb = smem_u32(dsm);

    const int tid = threadIdx.x;
    const int wid = tid >> 5;
    const int lane = tid & 31;
    const int wm = wid >> 2;
    const int wn = wid & 3;
    const int bm = blockIdx.y * BM;
    const int bn = blockIdx.x * BN;

    const __nv_bfloat16* mats[4] = {Ah, Am, Wh, Wm};

    auto load_stage = [&](int sg, int kt) {
        const int kbase = kt * BK;
#pragma unroll
        for (int i = 0; i < 8; i++) {
            int idx = tid + i * 256;
            int mat = idx >> 9;
            int w = idx & 511;
            int row = w >> 2;
            int c = w & 3;
            int grow = (mat < 2 ? bm : bn) + row;
            const __nv_bfloat16* gp = mats[mat] + (size_t)grow * D_MODEL + kbase + c * 8;
            uint32_t sa = sb + sg * STAGEB + mat * MATB + row * ROWB + c * 16;
            cp_async16(sa, gp);
        }
    };

    float acc[4][4][4];
#pragma unroll
    for (int a = 0; a < 4; a++)
#pragma unroll
        for (int b2 = 0; b2 < 4; b2++)
#pragma unroll
            for (int q = 0; q < 4; q++) acc[a][b2][q] = 0.f;

    load_stage(0, 0); CP_COMMIT();
    load_stage(1, 1); CP_COMMIT();

    const int lr = lane & 7;
    const int l3 = (lane >> 3) & 1;
    const int l4 = (lane >> 4) & 1;

    const int NK = D_MODEL / BK;
    for (int kt = 0; kt < NK; kt++) {
        const int sg = kt & 1;
        CP_WAIT1();
        __syncthreads();

        const uint32_t abase = sb + sg * STAGEB + (wm * 64) * ROWB;
        const uint32_t wbase = sb + sg * STAGEB + 2 * MATB + (wn * 32) * ROWB;

#pragma unroll
        for (int ks = 0; ks < 2; ks++) {
            uint32_t af[2][4][4];
            uint32_t bf_[2][4][2];
#pragma unroll
            for (int p = 0; p < 2; p++)
#pragma unroll
                for (int mt = 0; mt < 4; mt++) {
                    uint32_t addr = abase + p * MATB +
                                    (mt * 16 + lr + l3 * 8) * ROWB + ks * 32 + l4 * 16;
                    ldm_x4(af[p][mt][0], af[p][mt][1], af[p][mt][2], af[p][mt][3], addr);
                }
#pragma unroll
            for (int q = 0; q < 2; q++)
#pragma unroll
                for (int pr = 0; pr < 2; pr++) {
                    uint32_t r0, r1, r2, r3;
                    uint32_t addr = wbase + q * MATB +
                                    (pr * 16 + lr + l4 * 8) * ROWB + ks * 32 + l3 * 16;
                    ldm_x4(r0, r1, r2, r3, addr);
                    bf_[q][pr * 2 + 0][0] = r0;  bf_[q][pr * 2 + 0][1] = r1;
                    bf_[q][pr * 2 + 1][0] = r2;  bf_[q][pr * 2 + 1][1] = r3;
                }
#pragma unroll
            for (int mt = 0; mt < 4; mt++)
#pragma unroll
                for (int nt = 0; nt < 4; nt++) {
                    float* c = acc[mt][nt];
                    mma_bf16(c, af[0][mt], bf_[0][nt]);   // hh
                    mma_bf16(c, af[0][mt], bf_[1][nt]);   // hm
                    mma_bf16(c, af[1][mt], bf_[0][nt]);   // mh
                }
        }
        __syncthreads();
        if (kt + 2 < NK) load_stage(sg, kt + 2);
        CP_COMMIT();
    }

    const int qrow = lane >> 2;
    const int qcol = (lane & 3) * 2;
#pragma unroll
    for (int mt = 0; mt < 4; mt++) {
#pragma unroll
        for (int nt = 0; nt < 4; nt++) {
            const int col = bn + wn * 32 + nt * 8 + qcol;
            const float b0 = bias[col], b1 = bias[col + 1];
#pragma unroll
            for (int half = 0; half < 2; half++) {
                const int row = bm + wm * 64 + mt * 16 + qrow + half * 8;
                float v0 = acc[mt][nt][half * 2 + 0] + b0;
                float v1 = acc[mt][nt][half * 2 + 1] + b1;
                *(float2*)(C + (size_t)row * D_MODEL + col) = make_float2(v0, v1);
            }
        }
    }
}

// ---------------------------------------------------------------------------
// Launcher
// ---------------------------------------------------------------------------
extern "C" void kernel_launch(void* const* d_in, const int* in_sizes, int n_in,
                              void* d_out, int out_size)
{
    (void)in_sizes; (void)n_in; (void)out_size;
    const float* x  = (const float*)d_in[0];
    const float* Wq = (const float*)d_in[1];
    const float* bq = (const float*)d_in[2];
    const float* Wk = (const float*)d_in[3];
    const float* bk = (const float*)d_in[4];
    const float* Wv = (const float*)d_in[5];
    const float* bv = (const float*)d_in[6];
    const float* Wo = (const float*)d_in[7];
    const float* bo = (const float*)d_in[8];
    const float* gq = (const float*)d_in[9];
    const float* gk = (const float*)d_in[10];
    float* out = (float*)d_out;

    float *qp, *kp, *vp, *ap;
    __nv_bfloat16 *xh, *xm, *wh, *wm;
    cudaGetSymbolAddress((void**)&qp, g_q);
    cudaGetSymbolAddress((void**)&kp, g_k);
    cudaGetSymbolAddress((void**)&vp, g_v);
    cudaGetSymbolAddress((void**)&ap, g_attn);
    cudaGetSymbolAddress((void**)&xh, g_xh);
    cudaGetSymbolAddress((void**)&xm, g_xm);
    cudaGetSymbolAddress((void**)&wh, g_wh);
    cudaGetSymbolAddress((void**)&wm, g_wm);

    cudaFuncSetAttribute(flash_mma, cudaFuncAttributeMaxDynamicSharedMemorySize, FA_SMEM);
    cudaFuncSetAttribute(gemm_mma2, cudaFuncAttributeMaxDynamicSharedMemorySize, GEMM_SMEM);

    dim3 ggrid(D_MODEL / GBN, MTOT / GBM);

    gemm_bias_act<<<ggrid, 256>>>(x, Wq, bq, qp, D_MODEL, D_MODEL, 1);
    gemm_bias_act<<<ggrid, 256>>>(x, Wk, bk, kp, D_MODEL, D_MODEL, 1);
    gemm_bias_act<<<ggrid, 256>>>(x, Wv, bv, vp, D_MODEL, D_MODEL, 1);

    {
        dim3 nb(32, 8);
        int nrows = MTOT * NHEAD;
        qknorm_kernel<<<nrows / 8, nb>>>(qp, kp, gq, gk);
    }

    {
        dim3 fgrid(SEQ / 128, BATCH * NHEAD);
        flash_mma<<<fgrid, 256, FA_SMEM>>>(qp, kp, vp, ap);
    }

    const int nx4 = MTOT * D_MODEL / 4;
    const int nw4 = D_MODEL * D_MODEL / 4;
    split2<<<(nx4 + 255) / 256, 256>>>((const float4*)ap, (uint2*)xh, (uint2*)xm, nx4);
    split2<<<(nw4 + 255) / 256, 256>>>((const float4*)Wo, (uint2*)wh, (uint2*)wm, nw4);

    dim3 mgrid(D_MODEL / BN, MTOT / BM);
    gemm_mma2<<<mgrid, 256, GEMM_SMEM>>>(xh, xm, wh, wm, bo, out);
}

// round 6
// speedup vs baseline: 2.9540x; 1.4504x over previous
#include <cuda_runtime.h>
#include <cuda_bf16.h>
#include <math.h>
#include <stdint.h>

#define D_MODEL 1024
#define NHEAD 16
#define HEAD_DIM 64
#define BATCH 2
#define SEQ 2048
#define MTOT (BATCH * SEQ) /* 4096 */
#define DD (D_MODEL * D_MODEL)
#define FLAG_CAP (1 << 20)

// ---------------------------------------------------------------------------
// Scratch (device globals — no allocation allowed anywhere)
// ---------------------------------------------------------------------------
__device__ float g_q[MTOT * D_MODEL];
__device__ float g_k[MTOT * D_MODEL];
__device__ float g_v[MTOT * D_MODEL];
__device__ float g_attn[MTOT * D_MODEL];
__device__ __nv_bfloat16 g_xh[MTOT * D_MODEL];
__device__ __nv_bfloat16 g_xm[MTOT * D_MODEL];
__device__ __nv_bfloat16 g_wh[3 * DD];
__device__ __nv_bfloat16 g_wm[3 * DD];
__device__ uint32_t g_flags[FLAG_CAP];
__device__ int g_flagcnt;

// ---------------------------------------------------------------------------
// helpers
// ---------------------------------------------------------------------------
__device__ __forceinline__ uint32_t smem_u32(const void* p) {
    uint32_t a;
    asm("{ .reg .u64 t; cvta.to.shared.u64 t, %1; cvt.u32.u64 %0, t; }" : "=r"(a) : "l"(p));
    return a;
}
__device__ __forceinline__ void cp_async16(uint32_t sa, const void* ga) {
    asm volatile("cp.async.cg.shared.global [%0], [%1], 16;" :: "r"(sa), "l"(ga) : "memory");
}
#define CP_COMMIT() asm volatile("cp.async.commit_group;" ::: "memory")
#define CP_WAIT1()  asm volatile("cp.async.wait_group 1;" ::: "memory")

__device__ __forceinline__ void ldm_x4(uint32_t& r0, uint32_t& r1, uint32_t& r2, uint32_t& r3,
                                       uint32_t addr) {
    asm volatile("ldmatrix.sync.aligned.m8n8.x4.shared.b16 {%0,%1,%2,%3}, [%4];"
                 : "=r"(r0), "=r"(r1), "=r"(r2), "=r"(r3) : "r"(addr));
}
__device__ __forceinline__ void ldm_x4t(uint32_t& r0, uint32_t& r1, uint32_t& r2, uint32_t& r3,
                                        uint32_t addr) {
    asm volatile("ldmatrix.sync.aligned.m8n8.x4.trans.shared.b16 {%0,%1,%2,%3}, [%4];"
                 : "=r"(r0), "=r"(r1), "=r"(r2), "=r"(r3) : "r"(addr));
}
__device__ __forceinline__ void mma_bf16(float* c, const uint32_t* a, const uint32_t* b) {
    asm volatile(
        "mma.sync.aligned.m16n8k16.row.col.f32.bf16.bf16.f32 "
        "{%0,%1,%2,%3}, {%4,%5,%6,%7}, {%8,%9}, {%0,%1,%2,%3};"
        : "+f"(c[0]), "+f"(c[1]), "+f"(c[2]), "+f"(c[3])
        : "r"(a[0]), "r"(a[1]), "r"(a[2]), "r"(a[3]), "r"(b[0]), "r"(b[1]));
}

// ---------------------------------------------------------------------------
// misc small kernels
// ---------------------------------------------------------------------------
__global__ void zero_cnt_kernel(int* c) { *c = 0; }

__global__ void split2(const float4* __restrict__ src, uint2* __restrict__ H,
                       uint2* __restrict__ M, int n4)
{
    int i = blockIdx.x * blockDim.x + threadIdx.x;
    if (i >= n4) return;
    float4 x = src[i];
    float xs[4] = {x.x, x.y, x.z, x.w};
    uint16_t h[4], m[4];
#pragma unroll
    for (int j = 0; j < 4; j++) {
        __nv_bfloat16 hb = __float2bfloat16(xs[j]);
        float r1 = xs[j] - __bfloat162float(hb);
        __nv_bfloat16 mb = __float2bfloat16(r1);
        h[j] = __bfloat16_as_ushort(hb);
        m[j] = __bfloat16_as_ushort(mb);
    }
    H[i] = make_uint2((uint32_t)h[0] | ((uint32_t)h[1] << 16), (uint32_t)h[2] | ((uint32_t)h[3] << 16));
    M[i] = make_uint2((uint32_t)m[0] | ((uint32_t)m[1] << 16), (uint32_t)m[2] | ((uint32_t)m[3] << 16));
}

// ---------------------------------------------------------------------------
// QKV GEMM via mma.sync 2-way split (hh, hm, mh) + SFN epilogue with
// boundary flagging. grid.z selects Q/K/V. C[m,n] = sfn(A·W^T + bias).
// ---------------------------------------------------------------------------
#define BM 128
#define BN 128
#define BK 32
#define ROWB 80
#define MATB (128 * ROWB)
#define STAGEB (4 * MATB)
#define GEMM_SMEM (2 * STAGEB)
#define SFN_THR 1.5e-4f

__global__ __launch_bounds__(256, 1) void gemm_mma_sfn(
    const __nv_bfloat16* __restrict__ Ah, const __nv_bfloat16* __restrict__ Am,
    const __nv_bfloat16* __restrict__ WhB, const __nv_bfloat16* __restrict__ WmB,
    const float* __restrict__ bq, const float* __restrict__ bk, const float* __restrict__ bv,
    float* __restrict__ Cq, float* __restrict__ Ck, float* __restrict__ Cv,
    uint32_t* __restrict__ flags, int* __restrict__ flagcnt)
{
    extern __shared__ char dsm[];
    const uint32_t sb = smem_u32(dsm);

    const int z = blockIdx.z;
    const __nv_bfloat16* Wh = WhB + (size_t)z * DD;
    const __nv_bfloat16* Wm = WmB + (size_t)z * DD;
    const float* bias = (z == 0) ? bq : (z == 1) ? bk : bv;
    float* C = (z == 0) ? Cq : (z == 1) ? Ck : Cv;

    const int tid = threadIdx.x;
    const int wid = tid >> 5;
    const int lane = tid & 31;
    const int wm = wid >> 2;
    const int wn = wid & 3;
    const int bm = blockIdx.y * BM;
    const int bn = blockIdx.x * BN;

    const __nv_bfloat16* mats[4] = {Ah, Am, Wh, Wm};

    auto load_stage = [&](int sg, int kt) {
        const int kbase = kt * BK;
#pragma unroll
        for (int i = 0; i < 8; i++) {
            int idx = tid + i * 256;
            int mat = idx >> 9;
            int w = idx & 511;
            int row = w >> 2;
            int c = w & 3;
            int grow = (mat < 2 ? bm : bn) + row;
            const __nv_bfloat16* gp = mats[mat] + (size_t)grow * D_MODEL + kbase + c * 8;
            uint32_t sa = sb + sg * STAGEB + mat * MATB + row * ROWB + c * 16;
            cp_async16(sa, gp);
        }
    };

    float acc[4][4][4];
#pragma unroll
    for (int a = 0; a < 4; a++)
#pragma unroll
        for (int b2 = 0; b2 < 4; b2++)
#pragma unroll
            for (int q = 0; q < 4; q++) acc[a][b2][q] = 0.f;

    load_stage(0, 0); CP_COMMIT();
    load_stage(1, 1); CP_COMMIT();

    const int lr = lane & 7;
    const int l3 = (lane >> 3) & 1;
    const int l4 = (lane >> 4) & 1;

    const int NK = D_MODEL / BK;
    for (int kt = 0; kt < NK; kt++) {
        const int sg = kt & 1;
        CP_WAIT1();
        __syncthreads();

        const uint32_t abase = sb + sg * STAGEB + (wm * 64) * ROWB;
        const uint32_t wbase = sb + sg * STAGEB + 2 * MATB + (wn * 32) * ROWB;

#pragma unroll
        for (int ks = 0; ks < 2; ks++) {
            uint32_t af[2][4][4];
            uint32_t bf_[2][4][2];
#pragma unroll
            for (int p = 0; p < 2; p++)
#pragma unroll
                for (int mt = 0; mt < 4; mt++) {
                    uint32_t addr = abase + p * MATB +
                                    (mt * 16 + lr + l3 * 8) * ROWB + ks * 32 + l4 * 16;
                    ldm_x4(af[p][mt][0], af[p][mt][1], af[p][mt][2], af[p][mt][3], addr);
                }
#pragma unroll
            for (int q = 0; q < 2; q++)
#pragma unroll
                for (int pr = 0; pr < 2; pr++) {
                    uint32_t r0, r1, r2, r3;
                    uint32_t addr = wbase + q * MATB +
                                    (pr * 16 + lr + l4 * 8) * ROWB + ks * 32 + l3 * 16;
                    ldm_x4(r0, r1, r2, r3, addr);
                    bf_[q][pr * 2 + 0][0] = r0;  bf_[q][pr * 2 + 0][1] = r1;
                    bf_[q][pr * 2 + 1][0] = r2;  bf_[q][pr * 2 + 1][1] = r3;
                }
#pragma unroll
            for (int mt = 0; mt < 4; mt++)
#pragma unroll
                for (int nt = 0; nt < 4; nt++) {
                    float* c = acc[mt][nt];
                    mma_bf16(c, af[0][mt], bf_[0][nt]);   // hh
                    mma_bf16(c, af[0][mt], bf_[1][nt]);   // hm
                    mma_bf16(c, af[1][mt], bf_[0][nt]);   // mh
                }
        }
        __syncthreads();
        if (kt + 2 < NK) load_stage(sg, kt + 2);
        CP_COMMIT();
    }

    const int qrow = lane >> 2;
    const int qcol = (lane & 3) * 2;
#pragma unroll
    for (int mt = 0; mt < 4; mt++) {
#pragma unroll
        for (int nt = 0; nt < 4; nt++) {
            const int col = bn + wn * 32 + nt * 8 + qcol;
            const float b0 = bias[col], b1 = bias[col + 1];
#pragma unroll
            for (int half = 0; half < 2; half++) {
                const int row = bm + wm * 64 + mt * 16 + qrow + half * 8;
                float v0 = acc[mt][nt][half * 2 + 0] + b0;
                float v1 = acc[mt][nt][half * 2 + 1] + b1;
                // SFN with boundary flagging
                float t0 = v0 * 2.0f, t1 = v1 * 2.0f;
                float r0 = rintf(t0), r1 = rintf(t1);
                if (fabsf(t0 - r0) > 0.5f - SFN_THR) {
                    int idx = atomicAdd(flagcnt, 1);
                    if (idx < FLAG_CAP)
                        flags[idx] = ((uint32_t)z << 22) | ((uint32_t)row << 10) | (uint32_t)col;
                }
                if (fabsf(t1 - r1) > 0.5f - SFN_THR) {
                    int idx = atomicAdd(flagcnt, 1);
                    if (idx < FLAG_CAP)
                        flags[idx] = ((uint32_t)z << 22) | ((uint32_t)row << 10) | (uint32_t)(col + 1);
                }
                r0 = fminf(8.f, fmaxf(-8.f, r0));
                r1 = fminf(8.f, fmaxf(-8.f, r1));
                *(float2*)(C + (size_t)row * D_MODEL + col) = make_float2(r0 * 0.5f, r1 * 0.5f);
            }
        }
    }
}

// ---------------------------------------------------------------------------
// Fix-up: recompute flagged elements in sequential-class fp32 (warp per elem)
// ---------------------------------------------------------------------------
__global__ __launch_bounds__(256) void fixup_kernel(
    const float* __restrict__ x,
    const float* __restrict__ Wq, const float* __restrict__ Wk, const float* __restrict__ Wv,
    const float* __restrict__ bq, const float* __restrict__ bk, const float* __restrict__ bv,
    float* __restrict__ Q, float* __restrict__ K, float* __restrict__ V,
    const uint32_t* __restrict__ flags, const int* __restrict__ flagcnt)
{
    int n = *flagcnt;
    if (n > FLAG_CAP) n = FLAG_CAP;
    const int warp = (blockIdx.x * blockDim.x + threadIdx.x) >> 5;
    const int lane = threadIdx.x & 31;
    const int nw = (gridDim.x * blockDim.x) >> 5;

    for (int i = warp; i < n; i += nw) {
        uint32_t f = flags[i];
        int mat = f >> 22;
        int row = (f >> 10) & 0xFFF;
        int col = f & 0x3FF;
        const float* W = (mat == 0) ? Wq : (mat == 1) ? Wk : Wv;
        const float* bias = (mat == 0) ? bq : (mat == 1) ? bk : bv;
        float* C = (mat == 0) ? Q : (mat == 1) ? K : V;

        const float* xr = x + (size_t)row * D_MODEL;
        const float* wr = W + (size_t)col * D_MODEL;
        float s = 0.f;
        for (int j = lane * 4; j < D_MODEL; j += 128) {
            float4 a = *(const float4*)(xr + j);
            float4 b = *(const float4*)(wr + j);
            s = fmaf(a.x, b.x, s); s = fmaf(a.y, b.y, s);
            s = fmaf(a.z, b.z, s); s = fmaf(a.w, b.w, s);
        }
#pragma unroll
        for (int o = 16; o; o >>= 1) s += __shfl_xor_sync(0xffffffffu, s, o);
        if (lane == 0) {
            float c = s + bias[col];
            float r = fminf(8.f, fmaxf(-8.f, rintf(c * 2.f)));
            C[(size_t)row * D_MODEL + col] = r * 0.5f;
        }
    }
}

// ---------------------------------------------------------------------------
// qk-norm
// ---------------------------------------------------------------------------
__global__ void qknorm_kernel(float* __restrict__ Q, float* __restrict__ K,
                              const float* __restrict__ gq,
                              const float* __restrict__ gk)
{
    const int row  = blockIdx.x * blockDim.y + threadIdx.y;
    const int lane = threadIdx.x;

    float* qb = Q + (size_t)row * 64;
    float* kb = K + (size_t)row * 64;

    float2 xq = *(float2*)(qb + lane * 2);
    float2 xk = *(float2*)(kb + lane * 2);

    float sq = xq.x * xq.x + xq.y * xq.y;
    float sk = xk.x * xk.x + xk.y * xk.y;
#pragma unroll
    for (int o = 16; o; o >>= 1) {
        sq += __shfl_xor_sync(0xffffffffu, sq, o);
        sk += __shfl_xor_sync(0xffffffffu, sk, o);
    }
    const float invq = rsqrtf(sq * (1.0f / 64.0f) + 1e-6f);
    const float invk = rsqrtf(sk * (1.0f / 64.0f) + 1e-6f);

    const float gq0 = gq[lane * 2], gq1 = gq[lane * 2 + 1];
    const float gk0 = gk[lane * 2], gk1 = gk[lane * 2 + 1];

    xq.x = xq.x * invq * gq0;  xq.y = xq.y * invq * gq1;
    xk.x = xk.x * invk * gk0;  xk.y = xk.y * invk * gk1;

    *(float2*)(qb + lane * 2) = xq;
    *(float2*)(kb + lane * 2) = xk;
}

// ---------------------------------------------------------------------------
// Flash attention via mma.sync bf16 (proven round-5 version, unchanged)
// ---------------------------------------------------------------------------
#define AT_ROWB 144
#define FA_SMEM (2 * 128 * AT_ROWB)

__global__ __launch_bounds__(256, 1) void flash_mma(
    const float* __restrict__ Qg, const float* __restrict__ Kg,
    const float* __restrict__ Vg, float* __restrict__ Og)
{
    extern __shared__ char smp[];
    const uint32_t sb = smem_u32(smp);
    const int oQh = 0, oQl = 128 * AT_ROWB;
    const int oKh = 0, oKm = 64 * AT_ROWB, oV = 128 * AT_ROWB;

    const int tid = threadIdx.x, wid = tid >> 5, lane = tid & 31;
    const int b = blockIdx.y >> 4, h = blockIdx.y & 15;
    const int q0 = blockIdx.x * 128;

    const int lr = lane & 7, l3 = (lane >> 3) & 1, l4 = (lane >> 4) & 1;

    {
        const int row = tid >> 1;
        const int cb = (tid & 1) * 32;
        const float* qp = Qg + ((size_t)(b * SEQ + q0 + row)) * D_MODEL + h * HEAD_DIM + cb;
        char* dh_ = smp + oQh + row * AT_ROWB + cb * 2;
        char* dl_ = smp + oQl + row * AT_ROWB + cb * 2;
#pragma unroll
        for (int i = 0; i < 8; i++) {
            float4 f = *(const float4*)(qp + i * 4);
            f.x *= 0.125f; f.y *= 0.125f; f.z *= 0.125f; f.w *= 0.125f;
            __nv_bfloat162 h01 = __floats2bfloat162_rn(f.x, f.y);
            __nv_bfloat162 h23 = __floats2bfloat162_rn(f.z, f.w);
            __nv_bfloat162 l01 = __floats2bfloat162_rn(f.x - __bfloat162float(h01.x),
                                                       f.y - __bfloat162float(h01.y));
            __nv_bfloat162 l23 = __floats2bfloat162_rn(f.z - __bfloat162float(h23.x),
                                                       f.w - __bfloat162float(h23.y));
            *(__nv_bfloat162*)(dh_ + i * 8)     = h01;
            *(__nv_bfloat162*)(dh_ + i * 8 + 4) = h23;
            *(__nv_bfloat162*)(dl_ + i * 8)     = l01;
            *(__nv_bfloat162*)(dl_ + i * 8 + 4) = l23;
        }
    }
    __syncthreads();

    uint32_t qh[4][4], ql[4][4];
    {
        const int rbase = wid * 16 + lr + l3 * 8;
#pragma unroll
        for (int ks = 0; ks < 4; ks++) {
            ldm_x4(qh[ks][0], qh[ks][1], qh[ks][2], qh[ks][3],
                   sb + oQh + rbase * AT_ROWB + ks * 32 + l4 * 16);
            ldm_x4(ql[ks][0], ql[ks][1], ql[ks][2], ql[ks][3],
                   sb + oQl + rbase * AT_ROWB + ks * 32 + l4 * 16);
        }
    }
    __syncthreads();

    float m_lo = -INFINITY, m_hi = -INFINITY, l_lo = 0.f, l_hi = 0.f;
    float acc[8][4];
#pragma unroll
    for (int i = 0; i < 8; i++)
#pragma unroll
        for (int j = 0; j < 4; j++) acc[i][j] = 0.f;

    for (int kt = 0; kt < SEQ / 64; kt++) {
        {
            const int row = tid >> 2;
            const int cb = (tid & 3) * 16;
            const float* kp = Kg + ((size_t)(b * SEQ + kt * 64 + row)) * D_MODEL + h * HEAD_DIM + cb;
            const float* vp = Vg + ((size_t)(b * SEQ + kt * 64 + row)) * D_MODEL + h * HEAD_DIM + cb;
            char* dkh = smp + oKh + row * AT_ROWB + cb * 2;
            char* dkm = smp + oKm + row * AT_ROWB + cb * 2;
            char* dv  = smp + oV  + row * AT_ROWB + cb * 2;
#pragma unroll
            for (int i = 0; i < 4; i++) {
                float4 kf = *(const float4*)(kp + i * 4);
                __nv_bfloat162 kh01 = __floats2bfloat162_rn(kf.x, kf.y);
                __nv_bfloat162 kh23 = __floats2bfloat162_rn(kf.z, kf.w);
                __nv_bfloat162 km01 = __floats2bfloat162_rn(kf.x - __bfloat162float(kh01.x),
                                                            kf.y - __bfloat162float(kh01.y));
                __nv_bfloat162 km23 = __floats2bfloat162_rn(kf.z - __bfloat162float(kh23.x),
                                                            kf.w - __bfloat162float(kh23.y));
                *(__nv_bfloat162*)(dkh + i * 8)     = kh01;
                *(__nv_bfloat162*)(dkh + i * 8 + 4) = kh23;
                *(__nv_bfloat162*)(dkm + i * 8)     = km01;
                *(__nv_bfloat162*)(dkm + i * 8 + 4) = km23;
                float4 vf = *(const float4*)(vp + i * 4);
                *(__nv_bfloat162*)(dv + i * 8)     = __floats2bfloat162_rn(vf.x, vf.y);
                *(__nv_bfloat162*)(dv + i * 8 + 4) = __floats2bfloat162_rn(vf.z, vf.w);
            }
        }
        __syncthreads();

        float s[8][4];
#pragma unroll
        for (int i = 0; i < 8; i++)
#pragma unroll
            for (int j = 0; j < 4; j++) s[i][j] = 0.f;

#pragma unroll
        for (int np = 0; np < 4; np++) {
            const int rb = np * 16 + lr + l4 * 8;
#pragma unroll
            for (int ks = 0; ks < 4; ks++) {
                uint32_t bh0, bh1, bh2, bh3, bm0, bm1, bm2, bm3;
                ldm_x4(bh0, bh1, bh2, bh3, sb + oKh + rb * AT_ROWB + ks * 32 + l3 * 16);
                ldm_x4(bm0, bm1, bm2, bm3, sb + oKm + rb * AT_ROWB + ks * 32 + l3 * 16);
                uint32_t b0[2] = {bh0, bh1}, b1[2] = {bh2, bh3};
                uint32_t c0[2] = {bm0, bm1}, c1[2] = {bm2, bm3};
                mma_bf16(s[np * 2 + 0], qh[ks], b0);
                mma_bf16(s[np * 2 + 0], ql[ks], b0);
                mma_bf16(s[np * 2 + 0], qh[ks], c0);
                mma_bf16(s[np * 2 + 1], qh[ks], b1);
                mma_bf16(s[np * 2 + 1], ql[ks], b1);
                mma_bf16(s[np * 2 + 1], qh[ks], c1);
            }
        }

        float mx_lo = m_lo, mx_hi = m_hi;
#pragma unroll
        for (int i = 0; i < 8; i++) {
            mx_lo = fmaxf(mx_lo, fmaxf(s[i][0], s[i][1]));
            mx_hi = fmaxf(mx_hi, fmaxf(s[i][2], s[i][3]));
        }
        mx_lo = fmaxf(mx_lo, __shfl_xor_sync(0xffffffffu, mx_lo, 1));
        mx_lo = fmaxf(mx_lo, __shfl_xor_sync(0xffffffffu, mx_lo, 2));
        mx_hi = fmaxf(mx_hi, __shfl_xor_sync(0xffffffffu, mx_hi, 1));
        mx_hi = fmaxf(mx_hi, __shfl_xor_sync(0xffffffffu, mx_hi, 2));

        const float corr_lo = __expf(m_lo - mx_lo);
        const float corr_hi = __expf(m_hi - mx_hi);
        m_lo = mx_lo; m_hi = mx_hi;
        l_lo *= corr_lo; l_hi *= corr_hi;
#pragma unroll
        for (int i = 0; i < 8; i++) {
            acc[i][0] *= corr_lo; acc[i][1] *= corr_lo;
            acc[i][2] *= corr_hi; acc[i][3] *= corr_hi;
        }

        uint32_t ph[4][4], pm[4][4];
#pragma unroll
        for (int t = 0; t < 4; t++) {
#pragma unroll
            for (int half = 0; half < 2; half++) {
                const int nt = 2 * t + half;
                float p0 = __expf(s[nt][0] - mx_lo);
                float p1 = __expf(s[nt][1] - mx_lo);
                float p2 = __expf(s[nt][2] - mx_hi);
                float p3 = __expf(s[nt][3] - mx_hi);
                l_lo += p0 + p1; l_hi += p2 + p3;
                __nv_bfloat162 h01 = __floats2bfloat162_rn(p0, p1);
                __nv_bfloat162 h23 = __floats2bfloat162_rn(p2, p3);
                __nv_bfloat162 m01 = __floats2bfloat162_rn(p0 - __bfloat162float(h01.x),
                                                           p1 - __bfloat162float(h01.y));
                __nv_bfloat162 m23 = __floats2bfloat162_rn(p2 - __bfloat162float(h23.x),
                                                           p3 - __bfloat162float(h23.y));
                ph[t][half * 2 + 0] = *(uint32_t*)&h01;
                ph[t][half * 2 + 1] = *(uint32_t*)&h23;
                pm[t][half * 2 + 0] = *(uint32_t*)&m01;
                pm[t][half * 2 + 1] = *(uint32_t*)&m23;
            }
        }

#pragma unroll
        for (int np = 0; np < 4; np++) {
#pragma unroll
            for (int t = 0; t < 4; t++) {
                uint32_t v0, v1, v2, v3;
                ldm_x4t(v0, v1, v2, v3,
                        sb + oV + (t * 16 + lr + l3 * 8) * AT_ROWB + np * 32 + l4 * 16);
                uint32_t b0[2] = {v0, v1}, b1[2] = {v2, v3};
                mma_bf16(acc[np * 2 + 0], ph[t], b0);
                mma_bf16(acc[np * 2 + 0], pm[t], b0);
                mma_bf16(acc[np * 2 + 1], ph[t], b1);
                mma_bf16(acc[np * 2 + 1], pm[t], b1);
            }
        }
        __syncthreads();
    }

    l_lo += __shfl_xor_sync(0xffffffffu, l_lo, 1);
    l_lo += __shfl_xor_sync(0xffffffffu, l_lo, 2);
    l_hi += __shfl_xor_sync(0xffffffffu, l_hi, 1);
    l_hi += __shfl_xor_sync(0xffffffffu, l_hi, 2);
    const float inv_lo = 1.0f / l_lo;
    const float inv_hi = 1.0f / l_hi;

    const int r_lo = q0 + wid * 16 + (lane >> 2);
    const int r_hi = r_lo + 8;
    float* o_lo = Og + ((size_t)(b * SEQ + r_lo)) * D_MODEL + h * HEAD_DIM + (lane & 3) * 2;
    float* o_hi = Og + ((size_t)(b * SEQ + r_hi)) * D_MODEL + h * HEAD_DIM + (lane & 3) * 2;
#pragma unroll
    for (int nt = 0; nt < 8; nt++) {
        *(float2*)(o_lo + nt * 8) = make_float2(acc[nt][0] * inv_lo, acc[nt][1] * inv_lo);
        *(float2*)(o_hi + nt * 8) = make_float2(acc[nt][2] * inv_hi, acc[nt][3] * inv_hi);
    }
}

// ---------------------------------------------------------------------------
// Wo GEMM via mma.sync, 2-way split (hh, hm, mh):  C = A·W^T + bias
// ---------------------------------------------------------------------------
__global__ __launch_bounds__(256, 1) void gemm_mma2(
    const __nv_bfloat16* __restrict__ Ah, const __nv_bfloat16* __restrict__ Am,
    const __nv_bfloat16* __restrict__ Wh, const __nv_bfloat16* __restrict__ Wm,
    const float* __restrict__ bias, float* __restrict__ C)
{
    extern __shared__ char dsm[];
    const uint32_t sb = smem_u32(dsm);

    const int tid = threadIdx.x;
    const int wid = tid >> 5;
    const int lane = tid & 31;
    const int wm = wid >> 2;
    const int wn = wid & 3;
    const int bm = blockIdx.y * BM;
    const int bn = blockIdx.x * BN;

    const __nv_bfloat16* mats[4] = {Ah, Am, Wh, Wm};

    auto load_stage = [&](int sg, int kt) {
        const int kbase = kt * BK;
#pragma unroll
        for (int i = 0; i < 8; i++) {
            int idx = tid + i * 256;
            int mat = idx >> 9;
            int w = idx & 511;
            int row = w >> 2;
            int c = w & 3;
            int grow = (mat < 2 ? bm : bn) + row;
            const __nv_bfloat16* gp = mats[mat] + (size_t)grow * D_MODEL + kbase + c * 8;
            uint32_t sa = sb + sg * STAGEB + mat * MATB + row * ROWB + c * 16;
            cp_async16(sa, gp);
        }
    };

    float acc[4][4][4];
#pragma unroll
    for (int a = 0; a < 4; a++)
#pragma unroll
        for (int b2 = 0; b2 < 4; b2++)
#pragma unroll
            for (int q = 0; q < 4; q++) acc[a][b2][q] = 0.f;

    load_stage(0, 0); CP_COMMIT();
    load_stage(1, 1); CP_COMMIT();

    const int lr = lane & 7;
    const int l3 = (lane >> 3) & 1;
    const int l4 = (lane >> 4) & 1;

    const int NK = D_MODEL / BK;
    for (int kt = 0; kt < NK; kt++) {
        const int sg = kt & 1;
        CP_WAIT1();
        __syncthreads();

        const uint32_t abase = sb + sg * STAGEB + (wm * 64) * ROWB;
        const uint32_t wbase = sb + sg * STAGEB + 2 * MATB + (wn * 32) * ROWB;

#pragma unroll
        for (int ks = 0; ks < 2; ks++) {
            uint32_t af[2][4][4];
            uint32_t bf_[2][4][2];
#pragma unroll
            for (int p = 0; p < 2; p++)
#pragma unroll
                for (int mt = 0; mt < 4; mt++) {
                    uint32_t addr = abase + p * MATB +
                                    (mt * 16 + lr + l3 * 8) * ROWB + ks * 32 + l4 * 16;
                    ldm_x4(af[p][mt][0], af[p][mt][1], af[p][mt][2], af[p][mt][3], addr);
                }
#pragma unroll
            for (int q = 0; q < 2; q++)
#pragma unroll
                for (int pr = 0; pr < 2; pr++) {
                    uint32_t r0, r1, r2, r3;
                    uint32_t addr = wbase + q * MATB +
                                    (pr * 16 + lr + l4 * 8) * ROWB + ks * 32 + l3 * 16;
                    ldm_x4(r0, r1, r2, r3, addr);
                    bf_[q][pr * 2 + 0][0] = r0;  bf_[q][pr * 2 + 0][1] = r1;
                    bf_[q][pr * 2 + 1][0] = r2;  bf_[q][pr * 2 + 1][1] = r3;
                }
#pragma unroll
            for (int mt = 0; mt < 4; mt++)
#pragma unroll
                for (int nt = 0; nt < 4; nt++) {
                    float* c = acc[mt][nt];
                    mma_bf16(c, af[0][mt], bf_[0][nt]);
                    mma_bf16(c, af[0][mt], bf_[1][nt]);
                    mma_bf16(c, af[1][mt], bf_[0][nt]);
                }
        }
        __syncthreads();
        if (kt + 2 < NK) load_stage(sg, kt + 2);
        CP_COMMIT();
    }

    const int qrow = lane >> 2;
    const int qcol = (lane & 3) * 2;
#pragma unroll
    for (int mt = 0; mt < 4; mt++) {
#pragma unroll
        for (int nt = 0; nt < 4; nt++) {
            const int col = bn + wn * 32 + nt * 8 + qcol;
            const float b0 = bias[col], b1 = bias[col + 1];
#pragma unroll
            for (int half = 0; half < 2; half++) {
                const int row = bm + wm * 64 + mt * 16 + qrow + half * 8;
                float v0 = acc[mt][nt][half * 2 + 0] + b0;
                float v1 = acc[mt][nt][half * 2 + 1] + b1;
                *(float2*)(C + (size_t)row * D_MODEL + col) = make_float2(v0, v1);
            }
        }
    }
}

// ---------------------------------------------------------------------------
// Launcher
// ---------------------------------------------------------------------------
extern "C" void kernel_launch(void* const* d_in, const int* in_sizes, int n_in,
                              void* d_out, int out_size)
{
    (void)in_sizes; (void)n_in; (void)out_size;
    const float* x  = (const float*)d_in[0];
    const float* Wq = (const float*)d_in[1];
    const float* bq = (const float*)d_in[2];
    const float* Wk = (const float*)d_in[3];
    const float* bk = (const float*)d_in[4];
    const float* Wv = (const float*)d_in[5];
    const float* bv = (const float*)d_in[6];
    const float* Wo = (const float*)d_in[7];
    const float* bo = (const float*)d_in[8];
    const float* gq = (const float*)d_in[9];
    const float* gk = (const float*)d_in[10];
    float* out = (float*)d_out;

    float *qp, *kp, *vp, *ap;
    __nv_bfloat16 *xh, *xm, *wh, *wm;
    uint32_t* flags;
    int* flagcnt;
    cudaGetSymbolAddress((void**)&qp, g_q);
    cudaGetSymbolAddress((void**)&kp, g_k);
    cudaGetSymbolAddress((void**)&vp, g_v);
    cudaGetSymbolAddress((void**)&ap, g_attn);
    cudaGetSymbolAddress((void**)&xh, g_xh);
    cudaGetSymbolAddress((void**)&xm, g_xm);
    cudaGetSymbolAddress((void**)&wh, g_wh);
    cudaGetSymbolAddress((void**)&wm, g_wm);
    cudaGetSymbolAddress((void**)&flags, g_flags);
    cudaGetSymbolAddress((void**)&flagcnt, g_flagcnt);

    cudaFuncSetAttribute(gemm_mma_sfn, cudaFuncAttributeMaxDynamicSharedMemorySize, GEMM_SMEM);
    cudaFuncSetAttribute(gemm_mma2, cudaFuncAttributeMaxDynamicSharedMemorySize, GEMM_SMEM);
    cudaFuncSetAttribute(flash_mma, cudaFuncAttributeMaxDynamicSharedMemorySize, FA_SMEM);

    const int nx4 = MTOT * D_MODEL / 4;
    const int nw4 = DD / 4;

    zero_cnt_kernel<<<1, 1>>>(flagcnt);

    // splits: x once, all three weights
    split2<<<(nx4 + 255) / 256, 256>>>((const float4*)x, (uint2*)xh, (uint2*)xm, nx4);
    split2<<<(nw4 + 255) / 256, 256>>>((const float4*)Wq, (uint2*)wh, (uint2*)wm, nw4);
    split2<<<(nw4 + 255) / 256, 256>>>((const float4*)Wk, (uint2*)(wh + DD), (uint2*)(wm + DD), nw4);
    split2<<<(nw4 + 255) / 256, 256>>>((const float4*)Wv, (uint2*)(wh + 2 * DD), (uint2*)(wm + 2 * DD), nw4);

    {
        dim3 ggrid(D_MODEL / BN, MTOT / BM, 3);
        gemm_mma_sfn<<<ggrid, 256, GEMM_SMEM>>>(xh, xm, wh, wm, bq, bk, bv,
                                                qp, kp, vp, flags, flagcnt);
    }

    fixup_kernel<<<256, 256>>>(x, Wq, Wk, Wv, bq, bk, bv, qp, kp, vp, flags, flagcnt);

    {
        dim3 nb(32, 8);
        int nrows = MTOT * NHEAD;
        qknorm_kernel<<<nrows / 8, nb>>>(qp, kp, gq, gk);
    }

    {
        dim3 fgrid(SEQ / 128, BATCH * NHEAD);
        flash_mma<<<fgrid, 256, FA_SMEM>>>(qp, kp, vp, ap);
    }

    split2<<<(nx4 + 255) / 256, 256>>>((const float4*)ap, (uint2*)xh, (uint2*)xm, nx4);
    split2<<<(nw4 + 255) / 256, 256>>>((const float4*)Wo, (uint2*)wh, (uint2*)wm, nw4);

    dim3 mgrid(D_MODEL / BN, MTOT / BM);
    gemm_mma2<<<mgrid, 256, GEMM_SMEM>>>(xh, xm, wh, wm, bo, out);
}

// round 7
// speedup vs baseline: 3.4840x; 1.1794x over previous
#include <cuda_runtime.h>
#include <cuda_bf16.h>
#include <cuda_fp16.h>
#include <math.h>
#include <stdint.h>

#define D_MODEL 1024
#define NHEAD 16
#define HEAD_DIM 64
#define BATCH 2
#define SEQ 2048
#define MTOT (BATCH * SEQ) /* 4096 */
#define DD (D_MODEL * D_MODEL)
#define NBITS_WORDS (3 * MTOT * D_MODEL / 32)   /* 393216 */

// ---------------------------------------------------------------------------
// Scratch (device globals — no allocation allowed anywhere)
// ---------------------------------------------------------------------------
__device__ __half g_xhlf[MTOT * D_MODEL];          // x in fp16
__device__ __half g_whlf[3 * DD];                  // Wq/Wk/Wv in fp16
__device__ __half g_qh[MTOT * D_MODEL];            // Q (sfn, exact fp16)
__device__ __half g_kh[MTOT * D_MODEL];
__device__ __half g_vh[MTOT * D_MODEL];
__device__ __nv_bfloat16 g_ah[MTOT * D_MODEL];     // attn out hi (bf16)
__device__ __nv_bfloat16 g_am[MTOT * D_MODEL];     // attn out mid
__device__ __nv_bfloat16 g_wh[DD];                 // Wo hi
__device__ __nv_bfloat16 g_wm[DD];                 // Wo mid
__device__ uint32_t g_flagbits[NBITS_WORDS];

// ---------------------------------------------------------------------------
// helpers
// ---------------------------------------------------------------------------
__device__ __forceinline__ uint32_t smem_u32(const void* p) {
    uint32_t a;
    asm("{ .reg .u64 t; cvta.to.shared.u64 t, %1; cvt.u32.u64 %0, t; }" : "=r"(a) : "l"(p));
    return a;
}
__device__ __forceinline__ void cp_async16(uint32_t sa, const void* ga) {
    asm volatile("cp.async.cg.shared.global [%0], [%1], 16;" :: "r"(sa), "l"(ga) : "memory");
}
#define CP_COMMIT() asm volatile("cp.async.commit_group;" ::: "memory")
#define CP_WAIT1()  asm volatile("cp.async.wait_group 1;" ::: "memory")

__device__ __forceinline__ void ldm_x4(uint32_t& r0, uint32_t& r1, uint32_t& r2, uint32_t& r3,
                                       uint32_t addr) {
    asm volatile("ldmatrix.sync.aligned.m8n8.x4.shared.b16 {%0,%1,%2,%3}, [%4];"
                 : "=r"(r0), "=r"(r1), "=r"(r2), "=r"(r3) : "r"(addr));
}
__device__ __forceinline__ void ldm_x4t(uint32_t& r0, uint32_t& r1, uint32_t& r2, uint32_t& r3,
                                        uint32_t addr) {
    asm volatile("ldmatrix.sync.aligned.m8n8.x4.trans.shared.b16 {%0,%1,%2,%3}, [%4];"
                 : "=r"(r0), "=r"(r1), "=r"(r2), "=r"(r3) : "r"(addr));
}
__device__ __forceinline__ void mma_bf16(float* c, const uint32_t* a, const uint32_t* b) {
    asm volatile(
        "mma.sync.aligned.m16n8k16.row.col.f32.bf16.bf16.f32 "
        "{%0,%1,%2,%3}, {%4,%5,%6,%7}, {%8,%9}, {%0,%1,%2,%3};"
        : "+f"(c[0]), "+f"(c[1]), "+f"(c[2]), "+f"(c[3])
        : "r"(a[0]), "r"(a[1]), "r"(a[2]), "r"(a[3]), "r"(b[0]), "r"(b[1]));
}
__device__ __forceinline__ void mma_f16(float* c, const uint32_t* a, const uint32_t* b) {
    asm volatile(
        "mma.sync.aligned.m16n8k16.row.col.f32.f16.f16.f32 "
        "{%0,%1,%2,%3}, {%4,%5,%6,%7}, {%8,%9}, {%0,%1,%2,%3};"
        : "+f"(c[0]), "+f"(c[1]), "+f"(c[2]), "+f"(c[3])
        : "r"(a[0]), "r"(a[1]), "r"(a[2]), "r"(a[3]), "r"(b[0]), "r"(b[1]));
}

// ---------------------------------------------------------------------------
// small kernels
// ---------------------------------------------------------------------------
__global__ void conv_half(const float4* __restrict__ src, uint2* __restrict__ dst, int n4)
{
    int i = blockIdx.x * blockDim.x + threadIdx.x;
    if (i >= n4) return;
    float4 x = src[i];
    __half2 a = __floats2half2_rn(x.x, x.y);
    __half2 b = __floats2half2_rn(x.z, x.w);
    uint2 o;
    o.x = *(uint32_t*)&a;
    o.y = *(uint32_t*)&b;
    dst[i] = o;
}

__global__ void zero_bits(uint32_t* __restrict__ bits)
{
    int i = blockIdx.x * blockDim.x + threadIdx.x;
    if (i < NBITS_WORDS) bits[i] = 0;
}

__global__ void split2(const float4* __restrict__ src, uint2* __restrict__ H,
                       uint2* __restrict__ M, int n4)
{
    int i = blockIdx.x * blockDim.x + threadIdx.x;
    if (i >= n4) return;
    float4 x = src[i];
    float xs[4] = {x.x, x.y, x.z, x.w};
    uint16_t h[4], m[4];
#pragma unroll
    for (int j = 0; j < 4; j++) {
        __nv_bfloat16 hb = __float2bfloat16(xs[j]);
        float r1 = xs[j] - __bfloat162float(hb);
        __nv_bfloat16 mb = __float2bfloat16(r1);
        h[j] = __bfloat16_as_ushort(hb);
        m[j] = __bfloat16_as_ushort(mb);
    }
    H[i] = make_uint2((uint32_t)h[0] | ((uint32_t)h[1] << 16), (uint32_t)h[2] | ((uint32_t)h[3] << 16));
    M[i] = make_uint2((uint32_t)m[0] | ((uint32_t)m[1] << 16), (uint32_t)m[2] | ((uint32_t)m[3] << 16));
}

// ---------------------------------------------------------------------------
// QKV GEMM: plain fp16 mma (1 product) + SFN epilogue with bitmap flagging.
// grid.z selects Q/K/V. Output written as exact fp16 (multiples of 0.5).
// ---------------------------------------------------------------------------
#define BM 128
#define BN 128
#define BK 32
#define ROWB 80
#define HMATB (128 * ROWB)          /* 10240 */
#define HSTAGEB (2 * HMATB)         /* 20480 */
#define HGEMM_SMEM (2 * HSTAGEB)    /* 40960 */
#define SFN_THR 4.0e-3f

__global__ __launch_bounds__(256, 2) void gemm_hsfn(
    const __half* __restrict__ Ah, const __half* __restrict__ WhB,
    const float* __restrict__ bq, const float* __restrict__ bk, const float* __restrict__ bv,
    __half* __restrict__ Cq, __half* __restrict__ Ck, __half* __restrict__ Cv,
    uint32_t* __restrict__ bits)
{
    extern __shared__ char dsm[];
    const uint32_t sb = smem_u32(dsm);

    const int z = blockIdx.z;
    const __half* Wh = WhB + (size_t)z * DD;
    const float* bias = (z == 0) ? bq : (z == 1) ? bk : bv;
    __half* C = (z == 0) ? Cq : (z == 1) ? Ck : Cv;

    const int tid = threadIdx.x;
    const int wid = tid >> 5;
    const int lane = tid & 31;
    const int wm = wid >> 2;
    const int wn = wid & 3;
    const int bm = blockIdx.y * BM;
    const int bn = blockIdx.x * BN;

    const __half* mats[2] = {Ah, Wh};

    auto load_stage = [&](int sg, int kt) {
        const int kbase = kt * BK;
#pragma unroll
        for (int i = 0; i < 4; i++) {
            int idx = tid + i * 256;          // 0..1023
            int mat = idx >> 9;
            int w = idx & 511;
            int row = w >> 2;
            int c = w & 3;
            int grow = (mat ? bn : bm) + row;
            const __half* gp = mats[mat] + (size_t)grow * D_MODEL + kbase + c * 8;
            uint32_t sa = sb + sg * HSTAGEB + mat * HMATB + row * ROWB + c * 16;
            cp_async16(sa, gp);
        }
    };

    float acc[4][4][4];
#pragma unroll
    for (int a = 0; a < 4; a++)
#pragma unroll
        for (int b2 = 0; b2 < 4; b2++)
#pragma unroll
            for (int q = 0; q < 4; q++) acc[a][b2][q] = 0.f;

    load_stage(0, 0); CP_COMMIT();
    load_stage(1, 1); CP_COMMIT();

    const int lr = lane & 7;
    const int l3 = (lane >> 3) & 1;
    const int l4 = (lane >> 4) & 1;

    const int NK = D_MODEL / BK;
    for (int kt = 0; kt < NK; kt++) {
        const int sg = kt & 1;
        CP_WAIT1();
        __syncthreads();

        const uint32_t abase = sb + sg * HSTAGEB + (wm * 64) * ROWB;
        const uint32_t wbase = sb + sg * HSTAGEB + HMATB + (wn * 32) * ROWB;

#pragma unroll
        for (int ks = 0; ks < 2; ks++) {
            uint32_t af[4][4];
            uint32_t bf_[4][2];
#pragma unroll
            for (int mt = 0; mt < 4; mt++) {
                uint32_t addr = abase + (mt * 16 + lr + l3 * 8) * ROWB + ks * 32 + l4 * 16;
                ldm_x4(af[mt][0], af[mt][1], af[mt][2], af[mt][3], addr);
            }
#pragma unroll
            for (int pr = 0; pr < 2; pr++) {
                uint32_t r0, r1, r2, r3;
                uint32_t addr = wbase + (pr * 16 + lr + l4 * 8) * ROWB + ks * 32 + l3 * 16;
                ldm_x4(r0, r1, r2, r3, addr);
                bf_[pr * 2 + 0][0] = r0;  bf_[pr * 2 + 0][1] = r1;
                bf_[pr * 2 + 1][0] = r2;  bf_[pr * 2 + 1][1] = r3;
            }
#pragma unroll
            for (int mt = 0; mt < 4; mt++)
#pragma unroll
                for (int nt = 0; nt < 4; nt++)
                    mma_f16(acc[mt][nt], af[mt], bf_[nt]);
        }
        __syncthreads();
        if (kt + 2 < NK) load_stage(sg, kt + 2);
        CP_COMMIT();
    }

    const int qrow = lane >> 2;
    const int qcol = (lane & 3) * 2;
    const size_t zbase = (size_t)z * MTOT * D_MODEL;
#pragma unroll
    for (int mt = 0; mt < 4; mt++) {
#pragma unroll
        for (int nt = 0; nt < 4; nt++) {
            const int col = bn + wn * 32 + nt * 8 + qcol;
            const float b0 = bias[col], b1 = bias[col + 1];
#pragma unroll
            for (int half_ = 0; half_ < 2; half_++) {
                const int row = bm + wm * 64 + mt * 16 + qrow + half_ * 8;
                float v0 = acc[mt][nt][half_ * 2 + 0] + b0;
                float v1 = acc[mt][nt][half_ * 2 + 1] + b1;
                float t0 = v0 * 2.0f, t1 = v1 * 2.0f;
                float r0 = rintf(t0), r1 = rintf(t1);
                if (fabsf(t0 - r0) > 0.5f - SFN_THR) {
                    size_t g = zbase + (size_t)row * D_MODEL + col;
                    atomicOr(&bits[g >> 5], 1u << (g & 31));
                }
                if (fabsf(t1 - r1) > 0.5f - SFN_THR) {
                    size_t g = zbase + (size_t)row * D_MODEL + col + 1;
                    atomicOr(&bits[g >> 5], 1u << (g & 31));
                }
                r0 = fminf(8.f, fmaxf(-8.f, r0));
                r1 = fminf(8.f, fmaxf(-8.f, r1));
                __half2 o = __floats2half2_rn(r0 * 0.5f, r1 * 0.5f);
                *(__half2*)(C + (size_t)row * D_MODEL + col) = o;
            }
        }
    }
}

// ---------------------------------------------------------------------------
// Fix-up: recompute flagged elements with fp32 dot (warp per element)
// ---------------------------------------------------------------------------
__global__ __launch_bounds__(256) void fixup_kernel(
    const float* __restrict__ x,
    const float* __restrict__ Wq, const float* __restrict__ Wk, const float* __restrict__ Wv,
    const float* __restrict__ bq, const float* __restrict__ bk, const float* __restrict__ bv,
    __half* __restrict__ Q, __half* __restrict__ K, __half* __restrict__ V,
    const uint32_t* __restrict__ bits)
{
    const int warp = (blockIdx.x * blockDim.x + threadIdx.x) >> 5;
    const int lane = threadIdx.x & 31;
    const int nw = (gridDim.x * blockDim.x) >> 5;

    for (int w = warp; w < NBITS_WORDS; w += nw) {
        uint32_t word = bits[w];
        while (word) {
            int bit = __ffs(word) - 1;
            word &= word - 1;
            size_t g = ((size_t)w << 5) + bit;
            int z = (int)(g / ((size_t)MTOT * D_MODEL));
            size_t rem = g - (size_t)z * MTOT * D_MODEL;
            int row = (int)(rem >> 10);
            int col = (int)(rem & 1023);
            const float* W = (z == 0) ? Wq : (z == 1) ? Wk : Wv;
            const float* bias = (z == 0) ? bq : (z == 1) ? bk : bv;
            __half* C = (z == 0) ? Q : (z == 1) ? K : V;

            const float* xr = x + (size_t)row * D_MODEL;
            const float* wr = W + (size_t)col * D_MODEL;
            float s = 0.f;
            for (int j = lane * 4; j < D_MODEL; j += 128) {
                float4 a = *(const float4*)(xr + j);
                float4 b = *(const float4*)(wr + j);
                s = fmaf(a.x, b.x, s); s = fmaf(a.y, b.y, s);
                s = fmaf(a.z, b.z, s); s = fmaf(a.w, b.w, s);
            }
#pragma unroll
            for (int o = 16; o; o >>= 1) s += __shfl_xor_sync(0xffffffffu, s, o);
            if (lane == 0) {
                float c = s + bias[col];
                float r = fminf(8.f, fmaxf(-8.f, rintf(c * 2.f)));
                C[(size_t)row * D_MODEL + col] = __float2half(r * 0.5f);
            }
        }
    }
}

// ---------------------------------------------------------------------------
// Flash attention (bf16 mma core, proven) with qk-norm fused into staging and
// bf16 hi/mid split fused into the epilogue. Inputs Q/K/V are exact fp16.
// ---------------------------------------------------------------------------
#define AT_ROWB 144
#define FA_SMEM (2 * 128 * AT_ROWB)

__global__ __launch_bounds__(256, 1) void flash_mma(
    const __half* __restrict__ Qg, const __half* __restrict__ Kg,
    const __half* __restrict__ Vg,
    const float* __restrict__ gq, const float* __restrict__ gk,
    __nv_bfloat16* __restrict__ Oh, __nv_bfloat16* __restrict__ Om)
{
    extern __shared__ char smp[];
    const uint32_t sb = smem_u32(smp);
    const int oQh = 0, oQl = 128 * AT_ROWB;
    const int oKh = 0, oKm = 64 * AT_ROWB, oV = 128 * AT_ROWB;

    const int tid = threadIdx.x, wid = tid >> 5, lane = tid & 31;
    const int b = blockIdx.y >> 4, h = blockIdx.y & 15;
    const int q0 = blockIdx.x * 128;

    const int lr = lane & 7, l3 = (lane >> 3) & 1, l4 = (lane >> 4) & 1;

    // ---- stage Q: load fp16, rms-norm (fused qknorm), x gq x 0.125, split ----
    {
        const int row = tid >> 1;
        const int cb = (tid & 1) * 32;
        const __half* qp = Qg + ((size_t)(b * SEQ + q0 + row)) * D_MODEL + h * HEAD_DIM + cb;
        float v[32];
        const uint4* qp4 = (const uint4*)qp;
#pragma unroll
        for (int u = 0; u < 4; u++) {
            uint4 raw = qp4[u];
            const __half2* hp = (const __half2*)&raw;
#pragma unroll
            for (int j = 0; j < 4; j++) {
                float2 f = __half22float2(hp[j]);
                v[u * 8 + j * 2] = f.x;  v[u * 8 + j * 2 + 1] = f.y;
            }
        }
        float ss = 0.f;
#pragma unroll
        for (int i = 0; i < 32; i++) ss = fmaf(v[i], v[i], ss);
        ss += __shfl_xor_sync(0xffffffffu, ss, 1);
        const float inv = rsqrtf(ss * (1.0f / 64.0f) + 1e-6f) * 0.125f;

        char* dh_ = smp + oQh + row * AT_ROWB + cb * 2;
        char* dl_ = smp + oQl + row * AT_ROWB + cb * 2;
#pragma unroll
        for (int t = 0; t < 16; t++) {
            float a = v[t * 2]     * inv * __ldg(gq + cb + t * 2);
            float c = v[t * 2 + 1] * inv * __ldg(gq + cb + t * 2 + 1);
            __nv_bfloat162 hh = __floats2bfloat162_rn(a, c);
            __nv_bfloat162 ll = __floats2bfloat162_rn(a - __bfloat162float(hh.x),
                                                      c - __bfloat162float(hh.y));
            *(__nv_bfloat162*)(dh_ + t * 4) = hh;
            *(__nv_bfloat162*)(dl_ + t * 4) = ll;
        }
    }
    __syncthreads();

    uint32_t qh[4][4], ql[4][4];
    {
        const int rbase = wid * 16 + lr + l3 * 8;
#pragma unroll
        for (int ks = 0; ks < 4; ks++) {
            ldm_x4(qh[ks][0], qh[ks][1], qh[ks][2], qh[ks][3],
                   sb + oQh + rbase * AT_ROWB + ks * 32 + l4 * 16);
            ldm_x4(ql[ks][0], ql[ks][1], ql[ks][2], ql[ks][3],
                   sb + oQl + rbase * AT_ROWB + ks * 32 + l4 * 16);
        }
    }
    __syncthreads();

    float m_lo = -INFINITY, m_hi = -INFINITY, l_lo = 0.f, l_hi = 0.f;
    float acc[8][4];
#pragma unroll
    for (int i = 0; i < 8; i++)
#pragma unroll
        for (int j = 0; j < 4; j++) acc[i][j] = 0.f;

    for (int kt = 0; kt < SEQ / 64; kt++) {
        // ---- stage K (norm fused + split) and V (exact bf16) ----
        {
            const int row = tid >> 2;
            const int cb = (tid & 3) * 16;
            const __half* kp = Kg + ((size_t)(b * SEQ + kt * 64 + row)) * D_MODEL + h * HEAD_DIM + cb;
            const __half* vp = Vg + ((size_t)(b * SEQ + kt * 64 + row)) * D_MODEL + h * HEAD_DIM + cb;
            float kv[16], vv[16];
            const uint4* kp4 = (const uint4*)kp;
            const uint4* vp4 = (const uint4*)vp;
#pragma unroll
            for (int u = 0; u < 2; u++) {
                uint4 kr = kp4[u], vr = vp4[u];
                const __half2* khp = (const __half2*)&kr;
                const __half2* vhp = (const __half2*)&vr;
#pragma unroll
                for (int j = 0; j < 4; j++) {
                    float2 kf = __half22float2(khp[j]);
                    float2 vf = __half22float2(vhp[j]);
                    kv[u * 8 + j * 2] = kf.x;  kv[u * 8 + j * 2 + 1] = kf.y;
                    vv[u * 8 + j * 2] = vf.x;  vv[u * 8 + j * 2 + 1] = vf.y;
                }
            }
            float ss = 0.f;
#pragma unroll
            for (int i = 0; i < 16; i++) ss = fmaf(kv[i], kv[i], ss);
            ss += __shfl_xor_sync(0xffffffffu, ss, 1);
            ss += __shfl_xor_sync(0xffffffffu, ss, 2);
            const float inv = rsqrtf(ss * (1.0f / 64.0f) + 1e-6f);

            char* dkh = smp + oKh + row * AT_ROWB + cb * 2;
            char* dkm = smp + oKm + row * AT_ROWB + cb * 2;
            char* dv  = smp + oV  + row * AT_ROWB + cb * 2;
#pragma unroll
            for (int t = 0; t < 8; t++) {
                float a = kv[t * 2]     * inv * __ldg(gk + cb + t * 2);
                float c = kv[t * 2 + 1] * inv * __ldg(gk + cb + t * 2 + 1);
                __nv_bfloat162 hh = __floats2bfloat162_rn(a, c);
                __nv_bfloat162 mm = __floats2bfloat162_rn(a - __bfloat162float(hh.x),
                                                          c - __bfloat162float(hh.y));
                *(__nv_bfloat162*)(dkh + t * 4) = hh;
                *(__nv_bfloat162*)(dkm + t * 4) = mm;
                *(__nv_bfloat162*)(dv + t * 4) = __floats2bfloat162_rn(vv[t * 2], vv[t * 2 + 1]);
            }
        }
        __syncthreads();

        // ---- S = Qs·K^T (3 products) ----
        float s[8][4];
#pragma unroll
        for (int i = 0; i < 8; i++)
#pragma unroll
            for (int j = 0; j < 4; j++) s[i][j] = 0.f;

#pragma unroll
        for (int np = 0; np < 4; np++) {
            const int rb = np * 16 + lr + l4 * 8;
#pragma unroll
            for (int ks = 0; ks < 4; ks++) {
                uint32_t bh0, bh1, bh2, bh3, bm0, bm1, bm2, bm3;
                ldm_x4(bh0, bh1, bh2, bh3, sb + oKh + rb * AT_ROWB + ks * 32 + l3 * 16);
                ldm_x4(bm0, bm1, bm2, bm3, sb + oKm + rb * AT_ROWB + ks * 32 + l3 * 16);
                uint32_t b0[2] = {bh0, bh1}, b1[2] = {bh2, bh3};
                uint32_t c0[2] = {bm0, bm1}, c1[2] = {bm2, bm3};
                mma_bf16(s[np * 2 + 0], qh[ks], b0);
                mma_bf16(s[np * 2 + 0], ql[ks], b0);
                mma_bf16(s[np * 2 + 0], qh[ks], c0);
                mma_bf16(s[np * 2 + 1], qh[ks], b1);
                mma_bf16(s[np * 2 + 1], ql[ks], b1);
                mma_bf16(s[np * 2 + 1], qh[ks], c1);
            }
        }

        // ---- online softmax ----
        float mx_lo = m_lo, mx_hi = m_hi;
#pragma unroll
        for (int i = 0; i < 8; i++) {
            mx_lo = fmaxf(mx_lo, fmaxf(s[i][0], s[i][1]));
            mx_hi = fmaxf(mx_hi, fmaxf(s[i][2], s[i][3]));
        }
        mx_lo = fmaxf(mx_lo, __shfl_xor_sync(0xffffffffu, mx_lo, 1));
        mx_lo = fmaxf(mx_lo, __shfl_xor_sync(0xffffffffu, mx_lo, 2));
        mx_hi = fmaxf(mx_hi, __shfl_xor_sync(0xffffffffu, mx_hi, 1));
        mx_hi = fmaxf(mx_hi, __shfl_xor_sync(0xffffffffu, mx_hi, 2));

        const float corr_lo = __expf(m_lo - mx_lo);
        const float corr_hi = __expf(m_hi - mx_hi);
        m_lo = mx_lo; m_hi = mx_hi;
        l_lo *= corr_lo; l_hi *= corr_hi;
#pragma unroll
        for (int i = 0; i < 8; i++) {
            acc[i][0] *= corr_lo; acc[i][1] *= corr_lo;
            acc[i][2] *= corr_hi; acc[i][3] *= corr_hi;
        }

        uint32_t ph[4][4], pm[4][4];
#pragma unroll
        for (int t = 0; t < 4; t++) {
#pragma unroll
            for (int half_ = 0; half_ < 2; half_++) {
                const int nt = 2 * t + half_;
                float p0 = __expf(s[nt][0] - mx_lo);
                float p1 = __expf(s[nt][1] - mx_lo);
                float p2 = __expf(s[nt][2] - mx_hi);
                float p3 = __expf(s[nt][3] - mx_hi);
                l_lo += p0 + p1; l_hi += p2 + p3;
                __nv_bfloat162 h01 = __floats2bfloat162_rn(p0, p1);
                __nv_bfloat162 h23 = __floats2bfloat162_rn(p2, p3);
                __nv_bfloat162 m01 = __floats2bfloat162_rn(p0 - __bfloat162float(h01.x),
                                                           p1 - __bfloat162float(h01.y));
                __nv_bfloat162 m23 = __floats2bfloat162_rn(p2 - __bfloat162float(h23.x),
                                                           p3 - __bfloat162float(h23.y));
                ph[t][half_ * 2 + 0] = *(uint32_t*)&h01;
                ph[t][half_ * 2 + 1] = *(uint32_t*)&h23;
                pm[t][half_ * 2 + 0] = *(uint32_t*)&m01;
                pm[t][half_ * 2 + 1] = *(uint32_t*)&m23;
            }
        }

        // ---- acc += P·V ----
#pragma unroll
        for (int np = 0; np < 4; np++) {
#pragma unroll
            for (int t = 0; t < 4; t++) {
                uint32_t v0, v1, v2, v3;
                ldm_x4t(v0, v1, v2, v3,
                        sb + oV + (t * 16 + lr + l3 * 8) * AT_ROWB + np * 32 + l4 * 16);
                uint32_t b0[2] = {v0, v1}, b1[2] = {v2, v3};
                mma_bf16(acc[np * 2 + 0], ph[t], b0);
                mma_bf16(acc[np * 2 + 0], pm[t], b0);
                mma_bf16(acc[np * 2 + 1], ph[t], b1);
                mma_bf16(acc[np * 2 + 1], pm[t], b1);
            }
        }
        __syncthreads();
    }

    // ---- finalize: write bf16 hi/mid split directly (Wo GEMM input) ----
    l_lo += __shfl_xor_sync(0xffffffffu, l_lo, 1);
    l_lo += __shfl_xor_sync(0xffffffffu, l_lo, 2);
    l_hi += __shfl_xor_sync(0xffffffffu, l_hi, 1);
    l_hi += __shfl_xor_sync(0xffffffffu, l_hi, 2);
    const float inv_lo = 1.0f / l_lo;
    const float inv_hi = 1.0f / l_hi;

    const int r_lo = q0 + wid * 16 + (lane >> 2);
    const int r_hi = r_lo + 8;
    const size_t base_lo = ((size_t)(b * SEQ + r_lo)) * D_MODEL + h * HEAD_DIM + (lane & 3) * 2;
    const size_t base_hi = ((size_t)(b * SEQ + r_hi)) * D_MODEL + h * HEAD_DIM + (lane & 3) * 2;
#pragma unroll
    for (int nt = 0; nt < 8; nt++) {
        float a0 = acc[nt][0] * inv_lo, a1 = acc[nt][1] * inv_lo;
        float c0 = acc[nt][2] * inv_hi, c1 = acc[nt][3] * inv_hi;
        __nv_bfloat162 hlo = __floats2bfloat162_rn(a0, a1);
        __nv_bfloat162 mlo = __floats2bfloat162_rn(a0 - __bfloat162float(hlo.x),
                                                   a1 - __bfloat162float(hlo.y));
        __nv_bfloat162 hhi = __floats2bfloat162_rn(c0, c1);
        __nv_bfloat162 mhi = __floats2bfloat162_rn(c0 - __bfloat162float(hhi.x),
                                                   c1 - __bfloat162float(hhi.y));
        *(__nv_bfloat162*)(Oh + base_lo + nt * 8) = hlo;
        *(__nv_bfloat162*)(Om + base_lo + nt * 8) = mlo;
        *(__nv_bfloat162*)(Oh + base_hi + nt * 8) = hhi;
        *(__nv_bfloat162*)(Om + base_hi + nt * 8) = mhi;
    }
}

// ---------------------------------------------------------------------------
// Wo GEMM via mma.sync bf16, 2-way split (hh, hm, mh):  C = A·W^T + bias
// ---------------------------------------------------------------------------
#define MATB (128 * ROWB)
#define STAGEB (4 * MATB)
#define GEMM_SMEM (2 * STAGEB)

__global__ __launch_bounds__(256, 1) void gemm_mma2(
    const __nv_bfloat16* __restrict__ Ah, const __nv_bfloat16* __restrict__ Am,
    const __nv_bfloat16* __restrict__ Wh, const __nv_bfloat16* __restrict__ Wm,
    const float* __restrict__ bias, float* __restrict__ C)
{
    extern __shared__ char dsm[];
    const uint32_t sb = smem_u32(dsm);

    const int tid = threadIdx.x;
    const int wid = tid >> 5;
    const int lane = tid & 31;
    const int wm = wid >> 2;
    const int wn = wid & 3;
    const int bm = blockIdx.y * BM;
    const int bn = blockIdx.x * BN;

    const __nv_bfloat16* mats[4] = {Ah, Am, Wh, Wm};

    auto load_stage = [&](int sg, int kt) {
        const int kbase = kt * BK;
#pragma unroll
        for (int i = 0; i < 8; i++) {
            int idx = tid + i * 256;
            int mat = idx >> 9;
            int w = idx & 511;
            int row = w >> 2;
            int c = w & 3;
            int grow = (mat < 2 ? bm : bn) + row;
            const __nv_bfloat16* gp = mats[mat] + (size_t)grow * D_MODEL + kbase + c * 8;
            uint32_t sa = sb + sg * STAGEB + mat * MATB + row * ROWB + c * 16;
            cp_async16(sa, gp);
        }
    };

    float acc[4][4][4];
#pragma unroll
    for (int a = 0; a < 4; a++)
#pragma unroll
        for (int b2 = 0; b2 < 4; b2++)
#pragma unroll
            for (int q = 0; q < 4; q++) acc[a][b2][q] = 0.f;

    load_stage(0, 0); CP_COMMIT();
    load_stage(1, 1); CP_COMMIT();

    const int lr = lane & 7;
    const int l3 = (lane >> 3) & 1;
    const int l4 = (lane >> 4) & 1;

    const int NK = D_MODEL / BK;
    for (int kt = 0; kt < NK; kt++) {
        const int sg = kt & 1;
        CP_WAIT1();
        __syncthreads();

        const uint32_t abase = sb + sg * STAGEB + (wm * 64) * ROWB;
        const uint32_t wbase = sb + sg * STAGEB + 2 * MATB + (wn * 32) * ROWB;

#pragma unroll
        for (int ks = 0; ks < 2; ks++) {
            uint32_t af[2][4][4];
            uint32_t bf_[2][4][2];
#pragma unroll
            for (int p = 0; p < 2; p++)
#pragma unroll
                for (int mt = 0; mt < 4; mt++) {
                    uint32_t addr = abase + p * MATB +
                                    (mt * 16 + lr + l3 * 8) * ROWB + ks * 32 + l4 * 16;
                    ldm_x4(af[p][mt][0], af[p][mt][1], af[p][mt][2], af[p][mt][3], addr);
                }
#pragma unroll
            for (int q = 0; q < 2; q++)
#pragma unroll
                for (int pr = 0; pr < 2; pr++) {
                    uint32_t r0, r1, r2, r3;
                    uint32_t addr = wbase + q * MATB +
                                    (pr * 16 + lr + l4 * 8) * ROWB + ks * 32 + l3 * 16;
                    ldm_x4(r0, r1, r2, r3, addr);
                    bf_[q][pr * 2 + 0][0] = r0;  bf_[q][pr * 2 + 0][1] = r1;
                    bf_[q][pr * 2 + 1][0] = r2;  bf_[q][pr * 2 + 1][1] = r3;
                }
#pragma unroll
            for (int mt = 0; mt < 4; mt++)
#pragma unroll
                for (int nt = 0; nt < 4; nt++) {
                    float* c = acc[mt][nt];
                    mma_bf16(c, af[0][mt], bf_[0][nt]);
                    mma_bf16(c, af[0][mt], bf_[1][nt]);
                    mma_bf16(c, af[1][mt], bf_[0][nt]);
                }
        }
        __syncthreads();
        if (kt + 2 < NK) load_stage(sg, kt + 2);
        CP_COMMIT();
    }

    const int qrow = lane >> 2;
    const int qcol = (lane & 3) * 2;
#pragma unroll
    for (int mt = 0; mt < 4; mt++) {
#pragma unroll
        for (int nt = 0; nt < 4; nt++) {
            const int col = bn + wn * 32 + nt * 8 + qcol;
            const float b0 = bias[col], b1 = bias[col + 1];
#pragma unroll
            for (int half_ = 0; half_ < 2; half_++) {
                const int row = bm + wm * 64 + mt * 16 + qrow + half_ * 8;
                float v0 = acc[mt][nt][half_ * 2 + 0] + b0;
                float v1 = acc[mt][nt][half_ * 2 + 1] + b1;
                *(float2*)(C + (size_t)row * D_MODEL + col) = make_float2(v0, v1);
            }
        }
    }
}

// ---------------------------------------------------------------------------
// Launcher
// ---------------------------------------------------------------------------
extern "C" void kernel_launch(void* const* d_in, const int* in_sizes, int n_in,
                              void* d_out, int out_size)
{
    (void)in_sizes; (void)n_in; (void)out_size;
    const float* x  = (const float*)d_in[0];
    const float* Wq = (const float*)d_in[1];
    const float* bq = (const float*)d_in[2];
    const float* Wk = (const float*)d_in[3];
    const float* bk = (const float*)d_in[4];
    const float* Wv = (const float*)d_in[5];
    const float* bv = (const float*)d_in[6];
    const float* Wo = (const float*)d_in[7];
    const float* bo = (const float*)d_in[8];
    const float* gq = (const float*)d_in[9];
    const float* gk = (const float*)d_in[10];
    float* out = (float*)d_out;

    __half *xhlf, *whlf, *qh, *kh, *vh;
    __nv_bfloat16 *ah, *am, *wh, *wm;
    uint32_t* bits;
    cudaGetSymbolAddress((void**)&xhlf, g_xhlf);
    cudaGetSymbolAddress((void**)&whlf, g_whlf);
    cudaGetSymbolAddress((void**)&qh, g_qh);
    cudaGetSymbolAddress((void**)&kh, g_kh);
    cudaGetSymbolAddress((void**)&vh, g_vh);
    cudaGetSymbolAddress((void**)&ah, g_ah);
    cudaGetSymbolAddress((void**)&am, g_am);
    cudaGetSymbolAddress((void**)&wh, g_wh);
    cudaGetSymbolAddress((void**)&wm, g_wm);
    cudaGetSymbolAddress((void**)&bits, g_flagbits);

    cudaFuncSetAttribute(gemm_hsfn, cudaFuncAttributeMaxDynamicSharedMemorySize, HGEMM_SMEM);
    cudaFuncSetAttribute(gemm_mma2, cudaFuncAttributeMaxDynamicSharedMemorySize, GEMM_SMEM);
    cudaFuncSetAttribute(flash_mma, cudaFuncAttributeMaxDynamicSharedMemorySize, FA_SMEM);

    const int nx4 = MTOT * D_MODEL / 4;
    const int nw4 = DD / 4;

    // launches 1-5 (cheap) so ncu -s 5 profiles gemm_hsfn
    conv_half<<<(nx4 + 255) / 256, 256>>>((const float4*)x, (uint2*)xhlf, nx4);
    conv_half<<<(nw4 + 255) / 256, 256>>>((const float4*)Wq, (uint2*)whlf, nw4);
    conv_half<<<(nw4 + 255) / 256, 256>>>((const float4*)Wk, (uint2*)(whlf + DD), nw4);
    conv_half<<<(nw4 + 255) / 256, 256>>>((const float4*)Wv, (uint2*)(whlf + 2 * DD), nw4);
    zero_bits<<<(NBITS_WORDS + 255) / 256, 256>>>(bits);

    {
        dim3 ggrid(D_MODEL / BN, MTOT / BM, 3);
        gemm_hsfn<<<ggrid, 256, HGEMM_SMEM>>>(xhlf, whlf, bq, bk, bv, qh, kh, vh, bits);
    }

    fixup_kernel<<<512, 256>>>(x, Wq, Wk, Wv, bq, bk, bv, qh, kh, vh, bits);

    {
        dim3 fgrid(SEQ / 128, BATCH * NHEAD);
        flash_mma<<<fgrid, 256, FA_SMEM>>>(qh, kh, vh, gq, gk, ah, am);
    }

    split2<<<(nw4 + 255) / 256, 256>>>((const float4*)Wo, (uint2*)wh, (uint2*)wm, nw4);

    dim3 mgrid(D_MODEL / BN, MTOT / BM);
    gemm_mma2<<<mgrid, 256, GEMM_SMEM>>>(ah, am, wh, wm, bo, out);
}

// round 8
// speedup vs baseline: 3.8109x; 1.0938x over previous
#include <cuda_runtime.h>
#include <cuda_bf16.h>
#include <cuda_fp16.h>
#include <math.h>
#include <stdint.h>

#define D_MODEL 1024
#define NHEAD 16
#define HEAD_DIM 64
#define BATCH 2
#define SEQ 2048
#define MTOT (BATCH * SEQ) /* 4096 */
#define DD (D_MODEL * D_MODEL)
#define NBITS_WORDS (3 * MTOT * D_MODEL / 32)   /* 393216 */

// ---------------------------------------------------------------------------
// Scratch (device globals — no allocation allowed anywhere)
// ---------------------------------------------------------------------------
__device__ __half g_xhlf[MTOT * D_MODEL];          // x in fp16
__device__ __half g_whlf[3 * DD];                  // Wq/Wk/Wv in fp16
__device__ __half g_wo[DD];                        // Wo in fp16
__device__ __half g_qh[MTOT * D_MODEL];            // Q (sfn, exact fp16)
__device__ __half g_kh[MTOT * D_MODEL];
__device__ __half g_vh[MTOT * D_MODEL];
__device__ __half g_aat[MTOT * D_MODEL];           // attention output (fp16)
__device__ uint32_t g_flagbits[NBITS_WORDS];

// ---------------------------------------------------------------------------
// helpers
// ---------------------------------------------------------------------------
__device__ __forceinline__ uint32_t smem_u32(const void* p) {
    uint32_t a;
    asm("{ .reg .u64 t; cvta.to.shared.u64 t, %1; cvt.u32.u64 %0, t; }" : "=r"(a) : "l"(p));
    return a;
}
__device__ __forceinline__ void cp_async16(uint32_t sa, const void* ga) {
    asm volatile("cp.async.cg.shared.global [%0], [%1], 16;" :: "r"(sa), "l"(ga) : "memory");
}
#define CP_COMMIT() asm volatile("cp.async.commit_group;" ::: "memory")
#define CP_WAIT1()  asm volatile("cp.async.wait_group 1;" ::: "memory")

__device__ __forceinline__ void ldm_x4(uint32_t& r0, uint32_t& r1, uint32_t& r2, uint32_t& r3,
                                       uint32_t addr) {
    asm volatile("ldmatrix.sync.aligned.m8n8.x4.shared.b16 {%0,%1,%2,%3}, [%4];"
                 : "=r"(r0), "=r"(r1), "=r"(r2), "=r"(r3) : "r"(addr));
}
__device__ __forceinline__ void ldm_x4t(uint32_t& r0, uint32_t& r1, uint32_t& r2, uint32_t& r3,
                                        uint32_t addr) {
    asm volatile("ldmatrix.sync.aligned.m8n8.x4.trans.shared.b16 {%0,%1,%2,%3}, [%4];"
                 : "=r"(r0), "=r"(r1), "=r"(r2), "=r"(r3) : "r"(addr));
}
__device__ __forceinline__ void mma_bf16(float* c, const uint32_t* a, const uint32_t* b) {
    asm volatile(
        "mma.sync.aligned.m16n8k16.row.col.f32.bf16.bf16.f32 "
        "{%0,%1,%2,%3}, {%4,%5,%6,%7}, {%8,%9}, {%0,%1,%2,%3};"
        : "+f"(c[0]), "+f"(c[1]), "+f"(c[2]), "+f"(c[3])
        : "r"(a[0]), "r"(a[1]), "r"(a[2]), "r"(a[3]), "r"(b[0]), "r"(b[1]));
}
__device__ __forceinline__ void mma_f16(float* c, const uint32_t* a, const uint32_t* b) {
    asm volatile(
        "mma.sync.aligned.m16n8k16.row.col.f32.f16.f16.f32 "
        "{%0,%1,%2,%3}, {%4,%5,%6,%7}, {%8,%9}, {%0,%1,%2,%3};"
        : "+f"(c[0]), "+f"(c[1]), "+f"(c[2]), "+f"(c[3])
        : "r"(a[0]), "r"(a[1]), "r"(a[2]), "r"(a[3]), "r"(b[0]), "r"(b[1]));
}

// ---------------------------------------------------------------------------
// small kernels
// ---------------------------------------------------------------------------
__global__ void conv_half(const float4* __restrict__ src, uint2* __restrict__ dst, int n4)
{
    int i = blockIdx.x * blockDim.x + threadIdx.x;
    if (i >= n4) return;
    float4 x = src[i];
    __half2 a = __floats2half2_rn(x.x, x.y);
    __half2 b = __floats2half2_rn(x.z, x.w);
    uint2 o;
    o.x = *(uint32_t*)&a;
    o.y = *(uint32_t*)&b;
    dst[i] = o;
}

__global__ void zero_bits(uint32_t* __restrict__ bits)
{
    int i = blockIdx.x * blockDim.x + threadIdx.x;
    if (i < NBITS_WORDS) bits[i] = 0;
}

// ---------------------------------------------------------------------------
// QKV GEMM: plain fp16 mma (1 product) + SFN epilogue with bitmap flagging.
// grid.z selects Q/K/V. Output written as exact fp16 (multiples of 0.5).
// ---------------------------------------------------------------------------
#define BM 128
#define BN 128
#define BK 32
#define ROWB 80
#define HMATB (128 * ROWB)          /* 10240 */
#define HSTAGEB (2 * HMATB)         /* 20480 */
#define HGEMM_SMEM (2 * HSTAGEB)    /* 40960 */
#define SFN_THR 4.0e-3f

__global__ __launch_bounds__(256, 2) void gemm_hsfn(
    const __half* __restrict__ Ah, const __half* __restrict__ WhB,
    const float* __restrict__ bq, const float* __restrict__ bk, const float* __restrict__ bv,
    __half* __restrict__ Cq, __half* __restrict__ Ck, __half* __restrict__ Cv,
    uint32_t* __restrict__ bits)
{
    extern __shared__ char dsm[];
    const uint32_t sb = smem_u32(dsm);

    const int z = blockIdx.z;
    const __half* Wh = WhB + (size_t)z * DD;
    const float* bias = (z == 0) ? bq : (z == 1) ? bk : bv;
    __half* C = (z == 0) ? Cq : (z == 1) ? Ck : Cv;

    const int tid = threadIdx.x;
    const int wid = tid >> 5;
    const int lane = tid & 31;
    const int wm = wid >> 2;
    const int wn = wid & 3;
    const int bm = blockIdx.y * BM;
    const int bn = blockIdx.x * BN;

    const __half* mats[2] = {Ah, Wh};

    auto load_stage = [&](int sg, int kt) {
        const int kbase = kt * BK;
#pragma unroll
        for (int i = 0; i < 4; i++) {
            int idx = tid + i * 256;
            int mat = idx >> 9;
            int w = idx & 511;
            int row = w >> 2;
            int c = w & 3;
            int grow = (mat ? bn : bm) + row;
            const __half* gp = mats[mat] + (size_t)grow * D_MODEL + kbase + c * 8;
            uint32_t sa = sb + sg * HSTAGEB + mat * HMATB + row * ROWB + c * 16;
            cp_async16(sa, gp);
        }
    };

    float acc[4][4][4];
#pragma unroll
    for (int a = 0; a < 4; a++)
#pragma unroll
        for (int b2 = 0; b2 < 4; b2++)
#pragma unroll
            for (int q = 0; q < 4; q++) acc[a][b2][q] = 0.f;

    load_stage(0, 0); CP_COMMIT();
    load_stage(1, 1); CP_COMMIT();

    const int lr = lane & 7;
    const int l3 = (lane >> 3) & 1;
    const int l4 = (lane >> 4) & 1;

    const int NK = D_MODEL / BK;
    for (int kt = 0; kt < NK; kt++) {
        const int sg = kt & 1;
        CP_WAIT1();
        __syncthreads();

        const uint32_t abase = sb + sg * HSTAGEB + (wm * 64) * ROWB;
        const uint32_t wbase = sb + sg * HSTAGEB + HMATB + (wn * 32) * ROWB;

#pragma unroll
        for (int ks = 0; ks < 2; ks++) {
            uint32_t af[4][4];
            uint32_t bf_[4][2];
#pragma unroll
            for (int mt = 0; mt < 4; mt++) {
                uint32_t addr = abase + (mt * 16 + lr + l3 * 8) * ROWB + ks * 32 + l4 * 16;
                ldm_x4(af[mt][0], af[mt][1], af[mt][2], af[mt][3], addr);
            }
#pragma unroll
            for (int pr = 0; pr < 2; pr++) {
                uint32_t r0, r1, r2, r3;
                uint32_t addr = wbase + (pr * 16 + lr + l4 * 8) * ROWB + ks * 32 + l3 * 16;
                ldm_x4(r0, r1, r2, r3, addr);
                bf_[pr * 2 + 0][0] = r0;  bf_[pr * 2 + 0][1] = r1;
                bf_[pr * 2 + 1][0] = r2;  bf_[pr * 2 + 1][1] = r3;
            }
#pragma unroll
            for (int mt = 0; mt < 4; mt++)
#pragma unroll
                for (int nt = 0; nt < 4; nt++)
                    mma_f16(acc[mt][nt], af[mt], bf_[nt]);
        }
        __syncthreads();
        if (kt + 2 < NK) load_stage(sg, kt + 2);
        CP_COMMIT();
    }

    const int qrow = lane >> 2;
    const int qcol = (lane & 3) * 2;
    const size_t zbase = (size_t)z * MTOT * D_MODEL;
#pragma unroll
    for (int mt = 0; mt < 4; mt++) {
#pragma unroll
        for (int nt = 0; nt < 4; nt++) {
            const int col = bn + wn * 32 + nt * 8 + qcol;
            const float b0 = bias[col], b1 = bias[col + 1];
#pragma unroll
            for (int half_ = 0; half_ < 2; half_++) {
                const int row = bm + wm * 64 + mt * 16 + qrow + half_ * 8;
                float v0 = acc[mt][nt][half_ * 2 + 0] + b0;
                float v1 = acc[mt][nt][half_ * 2 + 1] + b1;
                float t0 = v0 * 2.0f, t1 = v1 * 2.0f;
                float r0 = rintf(t0), r1 = rintf(t1);
                if (fabsf(t0 - r0) > 0.5f - SFN_THR) {
                    size_t g = zbase + (size_t)row * D_MODEL + col;
                    atomicOr(&bits[g >> 5], 1u << (g & 31));
                }
                if (fabsf(t1 - r1) > 0.5f - SFN_THR) {
                    size_t g = zbase + (size_t)row * D_MODEL + col + 1;
                    atomicOr(&bits[g >> 5], 1u << (g & 31));
                }
                r0 = fminf(8.f, fmaxf(-8.f, r0));
                r1 = fminf(8.f, fmaxf(-8.f, r1));
                __half2 o = __floats2half2_rn(r0 * 0.5f, r1 * 0.5f);
                *(__half2*)(C + (size_t)row * D_MODEL + col) = o;
            }
        }
    }
}

// ---------------------------------------------------------------------------
// Fix-up: recompute flagged elements with fp32 dot (warp per element)
// ---------------------------------------------------------------------------
__global__ __launch_bounds__(256) void fixup_kernel(
    const float* __restrict__ x,
    const float* __restrict__ Wq, const float* __restrict__ Wk, const float* __restrict__ Wv,
    const float* __restrict__ bq, const float* __restrict__ bk, const float* __restrict__ bv,
    __half* __restrict__ Q, __half* __restrict__ K, __half* __restrict__ V,
    const uint32_t* __restrict__ bits)
{
    const int warp = (blockIdx.x * blockDim.x + threadIdx.x) >> 5;
    const int lane = threadIdx.x & 31;
    const int nw = (gridDim.x * blockDim.x) >> 5;

    for (int w = warp; w < NBITS_WORDS; w += nw) {
        uint32_t word = bits[w];
        while (word) {
            int bit = __ffs(word) - 1;
            word &= word - 1;
            size_t g = ((size_t)w << 5) + bit;
            int z = (int)(g / ((size_t)MTOT * D_MODEL));
            size_t rem = g - (size_t)z * MTOT * D_MODEL;
            int row = (int)(rem >> 10);
            int col = (int)(rem & 1023);
            const float* W = (z == 0) ? Wq : (z == 1) ? Wk : Wv;
            const float* bias = (z == 0) ? bq : (z == 1) ? bk : bv;
            __half* C = (z == 0) ? Q : (z == 1) ? K : V;

            const float* xr = x + (size_t)row * D_MODEL;
            const float* wr = W + (size_t)col * D_MODEL;
            float s = 0.f;
            for (int j = lane * 4; j < D_MODEL; j += 128) {
                float4 a = *(const float4*)(xr + j);
                float4 b = *(const float4*)(wr + j);
                s = fmaf(a.x, b.x, s); s = fmaf(a.y, b.y, s);
                s = fmaf(a.z, b.z, s); s = fmaf(a.w, b.w, s);
            }
#pragma unroll
            for (int o = 16; o; o >>= 1) s += __shfl_xor_sync(0xffffffffu, s, o);
            if (lane == 0) {
                float c = s + bias[col];
                float r = fminf(8.f, fmaxf(-8.f, rintf(c * 2.f)));
                C[(size_t)row * D_MODEL + col] = __float2half(r * 0.5f);
            }
        }
    }
}

// ---------------------------------------------------------------------------
// Flash attention (bf16 mma core) with fused qk-norm; fp16 output.
// ---------------------------------------------------------------------------
#define AT_ROWB 144
#define FA_SMEM (2 * 128 * AT_ROWB)

__global__ __launch_bounds__(256, 1) void flash_mma(
    const __half* __restrict__ Qg, const __half* __restrict__ Kg,
    const __half* __restrict__ Vg,
    const float* __restrict__ gq, const float* __restrict__ gk,
    __half* __restrict__ Og)
{
    extern __shared__ char smp[];
    const uint32_t sb = smem_u32(smp);
    const int oQh = 0, oQl = 128 * AT_ROWB;
    const int oKh = 0, oKm = 64 * AT_ROWB, oV = 128 * AT_ROWB;

    const int tid = threadIdx.x, wid = tid >> 5, lane = tid & 31;
    const int b = blockIdx.y >> 4, h = blockIdx.y & 15;
    const int q0 = blockIdx.x * 128;

    const int lr = lane & 7, l3 = (lane >> 3) & 1, l4 = (lane >> 4) & 1;

    // ---- stage Q: load fp16, rms-norm, x gq x 0.125, bf16 split ----
    {
        const int row = tid >> 1;
        const int cb = (tid & 1) * 32;
        const __half* qp = Qg + ((size_t)(b * SEQ + q0 + row)) * D_MODEL + h * HEAD_DIM + cb;
        float v[32];
        const uint4* qp4 = (const uint4*)qp;
#pragma unroll
        for (int u = 0; u < 4; u++) {
            uint4 raw = qp4[u];
            const __half2* hp = (const __half2*)&raw;
#pragma unroll
            for (int j = 0; j < 4; j++) {
                float2 f = __half22float2(hp[j]);
                v[u * 8 + j * 2] = f.x;  v[u * 8 + j * 2 + 1] = f.y;
            }
        }
        float ss = 0.f;
#pragma unroll
        for (int i = 0; i < 32; i++) ss = fmaf(v[i], v[i], ss);
        ss += __shfl_xor_sync(0xffffffffu, ss, 1);
        const float inv = rsqrtf(ss * (1.0f / 64.0f) + 1e-6f) * 0.125f;

        char* dh_ = smp + oQh + row * AT_ROWB + cb * 2;
        char* dl_ = smp + oQl + row * AT_ROWB + cb * 2;
#pragma unroll
        for (int t = 0; t < 16; t++) {
            float a = v[t * 2]     * inv * __ldg(gq + cb + t * 2);
            float c = v[t * 2 + 1] * inv * __ldg(gq + cb + t * 2 + 1);
            __nv_bfloat162 hh = __floats2bfloat162_rn(a, c);
            __nv_bfloat162 ll = __floats2bfloat162_rn(a - __bfloat162float(hh.x),
                                                      c - __bfloat162float(hh.y));
            *(__nv_bfloat162*)(dh_ + t * 4) = hh;
            *(__nv_bfloat162*)(dl_ + t * 4) = ll;
        }
    }
    __syncthreads();

    uint32_t qh[4][4], ql[4][4];
    {
        const int rbase = wid * 16 + lr + l3 * 8;
#pragma unroll
        for (int ks = 0; ks < 4; ks++) {
            ldm_x4(qh[ks][0], qh[ks][1], qh[ks][2], qh[ks][3],
                   sb + oQh + rbase * AT_ROWB + ks * 32 + l4 * 16);
            ldm_x4(ql[ks][0], ql[ks][1], ql[ks][2], ql[ks][3],
                   sb + oQl + rbase * AT_ROWB + ks * 32 + l4 * 16);
        }
    }
    __syncthreads();

    float m_lo = -INFINITY, m_hi = -INFINITY, l_lo = 0.f, l_hi = 0.f;
    float acc[8][4];
#pragma unroll
    for (int i = 0; i < 8; i++)
#pragma unroll
        for (int j = 0; j < 4; j++) acc[i][j] = 0.f;

    for (int kt = 0; kt < SEQ / 64; kt++) {
        {
            const int row = tid >> 2;
            const int cb = (tid & 3) * 16;
            const __half* kp = Kg + ((size_t)(b * SEQ + kt * 64 + row)) * D_MODEL + h * HEAD_DIM + cb;
            const __half* vp = Vg + ((size_t)(b * SEQ + kt * 64 + row)) * D_MODEL + h * HEAD_DIM + cb;
            float kv[16], vv[16];
            const uint4* kp4 = (const uint4*)kp;
            const uint4* vp4 = (const uint4*)vp;
#pragma unroll
            for (int u = 0; u < 2; u++) {
                uint4 kr = kp4[u], vr = vp4[u];
                const __half2* khp = (const __half2*)&kr;
                const __half2* vhp = (const __half2*)&vr;
#pragma unroll
                for (int j = 0; j < 4; j++) {
                    float2 kf = __half22float2(khp[j]);
                    float2 vf = __half22float2(vhp[j]);
                    kv[u * 8 + j * 2] = kf.x;  kv[u * 8 + j * 2 + 1] = kf.y;
                    vv[u * 8 + j * 2] = vf.x;  vv[u * 8 + j * 2 + 1] = vf.y;
                }
            }
            float ss = 0.f;
#pragma unroll
            for (int i = 0; i < 16; i++) ss = fmaf(kv[i], kv[i], ss);
            ss += __shfl_xor_sync(0xffffffffu, ss, 1);
            ss += __shfl_xor_sync(0xffffffffu, ss, 2);
            const float inv = rsqrtf(ss * (1.0f / 64.0f) + 1e-6f);

            char* dkh = smp + oKh + row * AT_ROWB + cb * 2;
            char* dkm = smp + oKm + row * AT_ROWB + cb * 2;
            char* dv  = smp + oV  + row * AT_ROWB + cb * 2;
#pragma unroll
            for (int t = 0; t < 8; t++) {
                float a = kv[t * 2]     * inv * __ldg(gk + cb + t * 2);
                float c = kv[t * 2 + 1] * inv * __ldg(gk + cb + t * 2 + 1);
                __nv_bfloat162 hh = __floats2bfloat162_rn(a, c);
                __nv_bfloat162 mm = __floats2bfloat162_rn(a - __bfloat162float(hh.x),
                                                          c - __bfloat162float(hh.y));
                *(__nv_bfloat162*)(dkh + t * 4) = hh;
                *(__nv_bfloat162*)(dkm + t * 4) = mm;
                *(__nv_bfloat162*)(dv + t * 4) = __floats2bfloat162_rn(vv[t * 2], vv[t * 2 + 1]);
            }
        }
        __syncthreads();

        float s[8][4];
#pragma unroll
        for (int i = 0; i < 8; i++)
#pragma unroll
            for (int j = 0; j < 4; j++) s[i][j] = 0.f;

#pragma unroll
        for (int np = 0; np < 4; np++) {
            const int rb = np * 16 + lr + l4 * 8;
#pragma unroll
            for (int ks = 0; ks < 4; ks++) {
                uint32_t bh0, bh1, bh2, bh3, bm0, bm1, bm2, bm3;
                ldm_x4(bh0, bh1, bh2, bh3, sb + oKh + rb * AT_ROWB + ks * 32 + l3 * 16);
                ldm_x4(bm0, bm1, bm2, bm3, sb + oKm + rb * AT_ROWB + ks * 32 + l3 * 16);
                uint32_t b0[2] = {bh0, bh1}, b1[2] = {bh2, bh3};
                uint32_t c0[2] = {bm0, bm1}, c1[2] = {bm2, bm3};
                mma_bf16(s[np * 2 + 0], qh[ks], b0);
                mma_bf16(s[np * 2 + 0], ql[ks], b0);
                mma_bf16(s[np * 2 + 0], qh[ks], c0);
                mma_bf16(s[np * 2 + 1], qh[ks], b1);
                mma_bf16(s[np * 2 + 1], ql[ks], b1);
                mma_bf16(s[np * 2 + 1], qh[ks], c1);
            }
        }

        float mx_lo = m_lo, mx_hi = m_hi;
#pragma unroll
        for (int i = 0; i < 8; i++) {
            mx_lo = fmaxf(mx_lo, fmaxf(s[i][0], s[i][1]));
            mx_hi = fmaxf(mx_hi, fmaxf(s[i][2], s[i][3]));
        }
        mx_lo = fmaxf(mx_lo, __shfl_xor_sync(0xffffffffu, mx_lo, 1));
        mx_lo = fmaxf(mx_lo, __shfl_xor_sync(0xffffffffu, mx_lo, 2));
        mx_hi = fmaxf(mx_hi, __shfl_xor_sync(0xffffffffu, mx_hi, 1));
        mx_hi = fmaxf(mx_hi, __shfl_xor_sync(0xffffffffu, mx_hi, 2));

        const float corr_lo = __expf(m_lo - mx_lo);
        const float corr_hi = __expf(m_hi - mx_hi);
        m_lo = mx_lo; m_hi = mx_hi;
        l_lo *= corr_lo; l_hi *= corr_hi;
#pragma unroll
        for (int i = 0; i < 8; i++) {
            acc[i][0] *= corr_lo; acc[i][1] *= corr_lo;
            acc[i][2] *= corr_hi; acc[i][3] *= corr_hi;
        }

        uint32_t ph[4][4], pm[4][4];
#pragma unroll
        for (int t = 0; t < 4; t++) {
#pragma unroll
            for (int half_ = 0; half_ < 2; half_++) {
                const int nt = 2 * t + half_;
                float p0 = __expf(s[nt][0] - mx_lo);
                float p1 = __expf(s[nt][1] - mx_lo);
                float p2 = __expf(s[nt][2] - mx_hi);
                float p3 = __expf(s[nt][3] - mx_hi);
                l_lo += p0 + p1; l_hi += p2 + p3;
                __nv_bfloat162 h01 = __floats2bfloat162_rn(p0, p1);
                __nv_bfloat162 h23 = __floats2bfloat162_rn(p2, p3);
                __nv_bfloat162 m01 = __floats2bfloat162_rn(p0 - __bfloat162float(h01.x),
                                                           p1 - __bfloat162float(h01.y));
                __nv_bfloat162 m23 = __floats2bfloat162_rn(p2 - __bfloat162float(h23.x),
                                                           p3 - __bfloat162float(h23.y));
                ph[t][half_ * 2 + 0] = *(uint32_t*)&h01;
                ph[t][half_ * 2 + 1] = *(uint32_t*)&h23;
                pm[t][half_ * 2 + 0] = *(uint32_t*)&m01;
                pm[t][half_ * 2 + 1] = *(uint32_t*)&m23;
            }
        }

#pragma unroll
        for (int np = 0; np < 4; np++) {
#pragma unroll
            for (int t = 0; t < 4; t++) {
                uint32_t v0, v1, v2, v3;
                ldm_x4t(v0, v1, v2, v3,
                        sb + oV + (t * 16 + lr + l3 * 8) * AT_ROWB + np * 32 + l4 * 16);
                uint32_t b0[2] = {v0, v1}, b1[2] = {v2, v3};
                mma_bf16(acc[np * 2 + 0], ph[t], b0);
                mma_bf16(acc[np * 2 + 0], pm[t], b0);
                mma_bf16(acc[np * 2 + 1], ph[t], b1);
                mma_bf16(acc[np * 2 + 1], pm[t], b1);
            }
        }
        __syncthreads();
    }

    // ---- finalize: write fp16 attention output ----
    l_lo += __shfl_xor_sync(0xffffffffu, l_lo, 1);
    l_lo += __shfl_xor_sync(0xffffffffu, l_lo, 2);
    l_hi += __shfl_xor_sync(0xffffffffu, l_hi, 1);
    l_hi += __shfl_xor_sync(0xffffffffu, l_hi, 2);
    const float inv_lo = 1.0f / l_lo;
    const float inv_hi = 1.0f / l_hi;

    const int r_lo = q0 + wid * 16 + (lane >> 2);
    const int r_hi = r_lo + 8;
    const size_t base_lo = ((size_t)(b * SEQ + r_lo)) * D_MODEL + h * HEAD_DIM + (lane & 3) * 2;
    const size_t base_hi = ((size_t)(b * SEQ + r_hi)) * D_MODEL + h * HEAD_DIM + (lane & 3) * 2;
#pragma unroll
    for (int nt = 0; nt < 8; nt++) {
        __half2 olo = __floats2half2_rn(acc[nt][0] * inv_lo, acc[nt][1] * inv_lo);
        __half2 ohi = __floats2half2_rn(acc[nt][2] * inv_hi, acc[nt][3] * inv_hi);
        *(__half2*)(Og + base_lo + nt * 8) = olo;
        *(__half2*)(Og + base_hi + nt * 8) = ohi;
    }
}

// ---------------------------------------------------------------------------
// Wo GEMM: plain fp16 mma (1 product), fp32 bias + output.
// ---------------------------------------------------------------------------
__global__ __launch_bounds__(256, 2) void gemm_out(
    const __half* __restrict__ Ah, const __half* __restrict__ Wh,
    const float* __restrict__ bias, float* __restrict__ C)
{
    extern __shared__ char dsm[];
    const uint32_t sb = smem_u32(dsm);

    const int tid = threadIdx.x;
    const int wid = tid >> 5;
    const int lane = tid & 31;
    const int wm = wid >> 2;
    const int wn = wid & 3;
    const int bm = blockIdx.y * BM;
    const int bn = blockIdx.x * BN;

    const __half* mats[2] = {Ah, Wh};

    auto load_stage = [&](int sg, int kt) {
        const int kbase = kt * BK;
#pragma unroll
        for (int i = 0; i < 4; i++) {
            int idx = tid + i * 256;
            int mat = idx >> 9;
            int w = idx & 511;
            int row = w >> 2;
            int c = w & 3;
            int grow = (mat ? bn : bm) + row;
            const __half* gp = mats[mat] + (size_t)grow * D_MODEL + kbase + c * 8;
            uint32_t sa = sb + sg * HSTAGEB + mat * HMATB + row * ROWB + c * 16;
            cp_async16(sa, gp);
        }
    };

    float acc[4][4][4];
#pragma unroll
    for (int a = 0; a < 4; a++)
#pragma unroll
        for (int b2 = 0; b2 < 4; b2++)
#pragma unroll
            for (int q = 0; q < 4; q++) acc[a][b2][q] = 0.f;

    load_stage(0, 0); CP_COMMIT();
    load_stage(1, 1); CP_COMMIT();

    const int lr = lane & 7;
    const int l3 = (lane >> 3) & 1;
    const int l4 = (lane >> 4) & 1;

    const int NK = D_MODEL / BK;
    for (int kt = 0; kt < NK; kt++) {
        const int sg = kt & 1;
        CP_WAIT1();
        __syncthreads();

        const uint32_t abase = sb + sg * HSTAGEB + (wm * 64) * ROWB;
        const uint32_t wbase = sb + sg * HSTAGEB + HMATB + (wn * 32) * ROWB;

#pragma unroll
        for (int ks = 0; ks < 2; ks++) {
            uint32_t af[4][4];
            uint32_t bf_[4][2];
#pragma unroll
            for (int mt = 0; mt < 4; mt++) {
                uint32_t addr = abase + (mt * 16 + lr + l3 * 8) * ROWB + ks * 32 + l4 * 16;
                ldm_x4(af[mt][0], af[mt][1], af[mt][2], af[mt][3], addr);
            }
#pragma unroll
            for (int pr = 0; pr < 2; pr++) {
                uint32_t r0, r1, r2, r3;
                uint32_t addr = wbase + (pr * 16 + lr + l4 * 8) * ROWB + ks * 32 + l3 * 16;
                ldm_x4(r0, r1, r2, r3, addr);
                bf_[pr * 2 + 0][0] = r0;  bf_[pr * 2 + 0][1] = r1;
                bf_[pr * 2 + 1][0] = r2;  bf_[pr * 2 + 1][1] = r3;
            }
#pragma unroll
            for (int mt = 0; mt < 4; mt++)
#pragma unroll
                for (int nt = 0; nt < 4; nt++)
                    mma_f16(acc[mt][nt], af[mt], bf_[nt]);
        }
        __syncthreads();
        if (kt + 2 < NK) load_stage(sg, kt + 2);
        CP_COMMIT();
    }

    const int qrow = lane >> 2;
    const int qcol = (lane & 3) * 2;
#pragma unroll
    for (int mt = 0; mt < 4; mt++) {
#pragma unroll
        for (int nt = 0; nt < 4; nt++) {
            const int col = bn + wn * 32 + nt * 8 + qcol;
            const float b0 = bias[col], b1 = bias[col + 1];
#pragma unroll
            for (int half_ = 0; half_ < 2; half_++) {
                const int row = bm + wm * 64 + mt * 16 + qrow + half_ * 8;
                float v0 = acc[mt][nt][half_ * 2 + 0] + b0;
                float v1 = acc[mt][nt][half_ * 2 + 1] + b1;
                *(float2*)(C + (size_t)row * D_MODEL + col) = make_float2(v0, v1);
            }
        }
    }
}

// ---------------------------------------------------------------------------
// Launcher
// ---------------------------------------------------------------------------
extern "C" void kernel_launch(void* const* d_in, const int* in_sizes, int n_in,
                              void* d_out, int out_size)
{
    (void)in_sizes; (void)n_in; (void)out_size;
    const float* x  = (const float*)d_in[0];
    const float* Wq = (const float*)d_in[1];
    const float* bq = (const float*)d_in[2];
    const float* Wk = (const float*)d_in[3];
    const float* bk = (const float*)d_in[4];
    const float* Wv = (const float*)d_in[5];
    const float* bv = (const float*)d_in[6];
    const float* Wo = (const float*)d_in[7];
    const float* bo = (const float*)d_in[8];
    const float* gq = (const float*)d_in[9];
    const float* gk = (const float*)d_in[10];
    float* out = (float*)d_out;

    __half *xhlf, *whlf, *wo, *qh, *kh, *vh, *aat;
    uint32_t* bits;
    cudaGetSymbolAddress((void**)&xhlf, g_xhlf);
    cudaGetSymbolAddress((void**)&whlf, g_whlf);
    cudaGetSymbolAddress((void**)&wo, g_wo);
    cudaGetSymbolAddress((void**)&qh, g_qh);
    cudaGetSymbolAddress((void**)&kh, g_kh);
    cudaGetSymbolAddress((void**)&vh, g_vh);
    cudaGetSymbolAddress((void**)&aat, g_aat);
    cudaGetSymbolAddress((void**)&bits, g_flagbits);

    cudaFuncSetAttribute(gemm_hsfn, cudaFuncAttributeMaxDynamicSharedMemorySize, HGEMM_SMEM);
    cudaFuncSetAttribute(gemm_out, cudaFuncAttributeMaxDynamicSharedMemorySize, HGEMM_SMEM);
    cudaFuncSetAttribute(flash_mma, cudaFuncAttributeMaxDynamicSharedMemorySize, FA_SMEM);

    const int nx4 = MTOT * D_MODEL / 4;
    const int nw4 = DD / 4;

    conv_half<<<(nx4 + 255) / 256, 256>>>((const float4*)x, (uint2*)xhlf, nx4);
    conv_half<<<(nw4 + 255) / 256, 256>>>((const float4*)Wq, (uint2*)whlf, nw4);
    conv_half<<<(nw4 + 255) / 256, 256>>>((const float4*)Wk, (uint2*)(whlf + DD), nw4);
    conv_half<<<(nw4 + 255) / 256, 256>>>((const float4*)Wv, (uint2*)(whlf + 2 * DD), nw4);
    conv_half<<<(nw4 + 255) / 256, 256>>>((const float4*)Wo, (uint2*)wo, nw4);
    zero_bits<<<(NBITS_WORDS + 255) / 256, 256>>>(bits);

    {
        dim3 ggrid(D_MODEL / BN, MTOT / BM, 3);
        gemm_hsfn<<<ggrid, 256, HGEMM_SMEM>>>(xhlf, whlf, bq, bk, bv, qh, kh, vh, bits);
    }

    fixup_kernel<<<512, 256>>>(x, Wq, Wk, Wv, bq, bk, bv, qh, kh, vh, bits);

    {
        dim3 fgrid(SEQ / 128, BATCH * NHEAD);
        flash_mma<<<fgrid, 256, FA_SMEM>>>(qh, kh, vh, gq, gk, aat);
    }

    {
        dim3 mgrid(D_MODEL / BN, MTOT / BM);
        gemm_out<<<mgrid, 256, HGEMM_SMEM>>>(aat, wo, bo, out);
    }
}

// round 10
// speedup vs baseline: 5.5424x; 1.4544x over previous
#include <cuda_runtime.h>
#include <cuda_bf16.h>
#include <cuda_fp16.h>
#include <math.h>
#include <stdint.h>

#define D_MODEL 1024
#define NHEAD 16
#define HEAD_DIM 64
#define BATCH 2
#define SEQ 2048
#define MTOT (BATCH * SEQ) /* 4096 */
#define DD (D_MODEL * D_MODEL)
#define NBITS_WORDS (3 * MTOT * D_MODEL / 32)   /* 393216 */

// ---------------------------------------------------------------------------
// Scratch (device globals — no allocation allowed anywhere)
// ---------------------------------------------------------------------------
__device__ __half g_xhlf[MTOT * D_MODEL];          // x in fp16
__device__ __half g_whlf[3 * DD];                  // Wq/Wk/Wv in fp16
__device__ __half g_wo[DD];                        // Wo in fp16
__device__ __half g_qh[MTOT * D_MODEL];            // Q (sfn, exact fp16)
__device__ __half g_kh[MTOT * D_MODEL];
__device__ __half g_vh[MTOT * D_MODEL];
__device__ __half g_aat[MTOT * D_MODEL];           // attention output (fp16)
__device__ uint32_t g_flagbits[NBITS_WORDS];

// ---------------------------------------------------------------------------
// helpers
// ---------------------------------------------------------------------------
__device__ __forceinline__ uint32_t smem_u32(const void* p) {
    uint32_t a;
    asm("{ .reg .u64 t; cvta.to.shared.u64 t, %1; cvt.u32.u64 %0, t; }" : "=r"(a) : "l"(p));
    return a;
}
__device__ __forceinline__ void cp_async16(uint32_t sa, const void* ga) {
    asm volatile("cp.async.cg.shared.global [%0], [%1], 16;" :: "r"(sa), "l"(ga) : "memory");
}
#define CP_COMMIT() asm volatile("cp.async.commit_group;" ::: "memory")
#define CP_WAIT1()  asm volatile("cp.async.wait_group 1;" ::: "memory")

__device__ __forceinline__ void ldm_x4(uint32_t& r0, uint32_t& r1, uint32_t& r2, uint32_t& r3,
                                       uint32_t addr) {
    asm volatile("ldmatrix.sync.aligned.m8n8.x4.shared.b16 {%0,%1,%2,%3}, [%4];"
                 : "=r"(r0), "=r"(r1), "=r"(r2), "=r"(r3) : "r"(addr));
}
__device__ __forceinline__ void ldm_x4t(uint32_t& r0, uint32_t& r1, uint32_t& r2, uint32_t& r3,
                                        uint32_t addr) {
    asm volatile("ldmatrix.sync.aligned.m8n8.x4.trans.shared.b16 {%0,%1,%2,%3}, [%4];"
                 : "=r"(r0), "=r"(r1), "=r"(r2), "=r"(r3) : "r"(addr));
}
__device__ __forceinline__ void mma_f16(float* c, const uint32_t* a, const uint32_t* b) {
    asm volatile(
        "mma.sync.aligned.m16n8k16.row.col.f32.f16.f16.f32 "
        "{%0,%1,%2,%3}, {%4,%5,%6,%7}, {%8,%9}, {%0,%1,%2,%3};"
        : "+f"(c[0]), "+f"(c[1]), "+f"(c[2]), "+f"(c[3])
        : "r"(a[0]), "r"(a[1]), "r"(a[2]), "r"(a[3]), "r"(b[0]), "r"(b[1]));
}

// ---------------------------------------------------------------------------
// small kernels
// ---------------------------------------------------------------------------
__device__ __forceinline__ uint2 cvt_quad(float4 x) {
    __half2 a = __floats2half2_rn(x.x, x.y);
    __half2 b = __floats2half2_rn(x.z, x.w);
    uint2 o;
    o.x = *(uint32_t*)&a;
    o.y = *(uint32_t*)&b;
    return o;
}

__global__ void conv_all(const float4* __restrict__ x,
                         const float4* __restrict__ wq, const float4* __restrict__ wk,
                         const float4* __restrict__ wv, const float4* __restrict__ wo,
                         uint2* __restrict__ xh, uint2* __restrict__ whlf,
                         uint2* __restrict__ woh, int nx4, int nw4)
{
    int i = blockIdx.x * blockDim.x + threadIdx.x;
    if (i < nx4) { xh[i] = cvt_quad(x[i]); return; }
    i -= nx4;
    if (i < nw4) { whlf[i] = cvt_quad(wq[i]); return; }
    i -= nw4;
    if (i < nw4) { whlf[nw4 + i] = cvt_quad(wk[i]); return; }
    i -= nw4;
    if (i < nw4) { whlf[2 * nw4 + i] = cvt_quad(wv[i]); return; }
    i -= nw4;
    if (i < nw4) woh[i] = cvt_quad(wo[i]);
}

__global__ void zero_bits(uint32_t* __restrict__ bits)
{
    int i = blockIdx.x * blockDim.x + threadIdx.x;
    if (i < NBITS_WORDS) bits[i] = 0;
}

// ---------------------------------------------------------------------------
// QKV GEMM: plain fp16 mma (1 product) + SFN epilogue with bitmap flagging.
// ---------------------------------------------------------------------------
#define BM 128
#define BN 128
#define BK 32
#define ROWB 80
#define HMATB (128 * ROWB)
#define HSTAGEB (2 * HMATB)
#define HGEMM_SMEM (2 * HSTAGEB)
#define SFN_THR 4.0e-3f            /* REVERT: 4e-3 window (zero escapes proven) */

__global__ __launch_bounds__(256, 2) void gemm_hsfn(
    const __half* __restrict__ Ah, const __half* __restrict__ WhB,
    const float* __restrict__ bq, const float* __restrict__ bk, const float* __restrict__ bv,
    __half* __restrict__ Cq, __half* __restrict__ Ck, __half* __restrict__ Cv,
    uint32_t* __restrict__ bits)
{
    extern __shared__ char dsm[];
    const uint32_t sb = smem_u32(dsm);

    const int z = blockIdx.z;
    const __half* Wh = WhB + (size_t)z * DD;
    const float* bias = (z == 0) ? bq : (z == 1) ? bk : bv;
    __half* C = (z == 0) ? Cq : (z == 1) ? Ck : Cv;

    const int tid = threadIdx.x;
    const int wid = tid >> 5;
    const int lane = tid & 31;
    const int wm = wid >> 2;
    const int wn = wid & 3;
    const int bm = blockIdx.y * BM;
    const int bn = blockIdx.x * BN;

    const __half* mats[2] = {Ah, Wh};

    auto load_stage = [&](int sg, int kt) {
        const int kbase = kt * BK;
#pragma unroll
        for (int i = 0; i < 4; i++) {
            int idx = tid + i * 256;
            int mat = idx >> 9;
            int w = idx & 511;
            int row = w >> 2;
            int c = w & 3;
            int grow = (mat ? bn : bm) + row;
            const __half* gp = mats[mat] + (size_t)grow * D_MODEL + kbase + c * 8;
            uint32_t sa = sb + sg * HSTAGEB + mat * HMATB + row * ROWB + c * 16;
            cp_async16(sa, gp);
        }
    };

    float acc[4][4][4];
#pragma unroll
    for (int a = 0; a < 4; a++)
#pragma unroll
        for (int b2 = 0; b2 < 4; b2++)
#pragma unroll
            for (int q = 0; q < 4; q++) acc[a][b2][q] = 0.f;

    load_stage(0, 0); CP_COMMIT();
    load_stage(1, 1); CP_COMMIT();

    const int lr = lane & 7;
    const int l3 = (lane >> 3) & 1;
    const int l4 = (lane >> 4) & 1;

    const int NK = D_MODEL / BK;
    for (int kt = 0; kt < NK; kt++) {
        const int sg = kt & 1;
        CP_WAIT1();
        __syncthreads();

        const uint32_t abase = sb + sg * HSTAGEB + (wm * 64) * ROWB;
        const uint32_t wbase = sb + sg * HSTAGEB + HMATB + (wn * 32) * ROWB;

#pragma unroll
        for (int ks = 0; ks < 2; ks++) {
            uint32_t af[4][4];
            uint32_t bf_[4][2];
#pragma unroll
            for (int mt = 0; mt < 4; mt++) {
                uint32_t addr = abase + (mt * 16 + lr + l3 * 8) * ROWB + ks * 32 + l4 * 16;
                ldm_x4(af[mt][0], af[mt][1], af[mt][2], af[mt][3], addr);
            }
#pragma unroll
            for (int pr = 0; pr < 2; pr++) {
                uint32_t r0, r1, r2, r3;
                uint32_t addr = wbase + (pr * 16 + lr + l4 * 8) * ROWB + ks * 32 + l3 * 16;
                ldm_x4(r0, r1, r2, r3, addr);
                bf_[pr * 2 + 0][0] = r0;  bf_[pr * 2 + 0][1] = r1;
                bf_[pr * 2 + 1][0] = r2;  bf_[pr * 2 + 1][1] = r3;
            }
#pragma unroll
            for (int mt = 0; mt < 4; mt++)
#pragma unroll
                for (int nt = 0; nt < 4; nt++)
                    mma_f16(acc[mt][nt], af[mt], bf_[nt]);
        }
        __syncthreads();
        if (kt + 2 < NK) load_stage(sg, kt + 2);
        CP_COMMIT();
    }

    const int qrow = lane >> 2;
    const int qcol = (lane & 3) * 2;
    const size_t zbase = (size_t)z * MTOT * D_MODEL;
#pragma unroll
    for (int mt = 0; mt < 4; mt++) {
#pragma unroll
        for (int nt = 0; nt < 4; nt++) {
            const int col = bn + wn * 32 + nt * 8 + qcol;
            const float b0 = bias[col], b1 = bias[col + 1];
#pragma unroll
            for (int half_ = 0; half_ < 2; half_++) {
                const int row = bm + wm * 64 + mt * 16 + qrow + half_ * 8;
                float v0 = acc[mt][nt][half_ * 2 + 0] + b0;
                float v1 = acc[mt][nt][half_ * 2 + 1] + b1;
                float t0 = v0 * 2.0f, t1 = v1 * 2.0f;
                float r0 = rintf(t0), r1 = rintf(t1);
                if (fabsf(t0 - r0) > 0.5f - SFN_THR) {
                    size_t g = zbase + (size_t)row * D_MODEL + col;
                    atomicOr(&bits[g >> 5], 1u << (g & 31));
                }
                if (fabsf(t1 - r1) > 0.5f - SFN_THR) {
                    size_t g = zbase + (size_t)row * D_MODEL + col + 1;
                    atomicOr(&bits[g >> 5], 1u << (g & 31));
                }
                r0 = fminf(8.f, fmaxf(-8.f, r0));
                r1 = fminf(8.f, fmaxf(-8.f, r1));
                __half2 o = __floats2half2_rn(r0 * 0.5f, r1 * 0.5f);
                *(__half2*)(C + (size_t)row * D_MODEL + col) = o;
            }
        }
    }
}

// ---------------------------------------------------------------------------
// Fix-up: recompute flagged elements with fp32 dot (warp per element).
// Latency-optimized: fully unrolled loads (MLP=16), ~3 elems/warp via big grid.
// ---------------------------------------------------------------------------
__global__ __launch_bounds__(256) void fixup_kernel(
    const float* __restrict__ x,
    const float* __restrict__ Wq, const float* __restrict__ Wk, const float* __restrict__ Wv,
    const float* __restrict__ bq, const float* __restrict__ bk, const float* __restrict__ bv,
    __half* __restrict__ Q, __half* __restrict__ K, __half* __restrict__ V,
    const uint32_t* __restrict__ bits)
{
    const int warp = (blockIdx.x * blockDim.x + threadIdx.x) >> 5;
    const int lane = threadIdx.x & 31;
    const int nw = (gridDim.x * blockDim.x) >> 5;

    for (int w = warp; w < NBITS_WORDS; w += nw) {
        uint32_t word = bits[w];
        while (word) {
            int bit = __ffs(word) - 1;
            word &= word - 1;
            size_t g = ((size_t)w << 5) + bit;
            int z = (int)(g / ((size_t)MTOT * D_MODEL));
            size_t rem = g - (size_t)z * MTOT * D_MODEL;
            int row = (int)(rem >> 10);
            int col = (int)(rem & 1023);
            const float* W = (z == 0) ? Wq : (z == 1) ? Wk : Wv;
            const float* bias = (z == 0) ? bq : (z == 1) ? bk : bv;
            __half* C = (z == 0) ? Q : (z == 1) ? K : V;

            const float* xr = x + (size_t)row * D_MODEL;
            const float* wr = W + (size_t)col * D_MODEL;
            float4 av[8], bv_[8];
#pragma unroll
            for (int u = 0; u < 8; u++) {
                av[u]  = *(const float4*)(xr + lane * 4 + u * 128);
                bv_[u] = *(const float4*)(wr + lane * 4 + u * 128);
            }
            float s = 0.f;
#pragma unroll
            for (int u = 0; u < 8; u++) {
                s = fmaf(av[u].x, bv_[u].x, s); s = fmaf(av[u].y, bv_[u].y, s);
                s = fmaf(av[u].z, bv_[u].z, s); s = fmaf(av[u].w, bv_[u].w, s);
            }
#pragma unroll
            for (int o = 16; o; o >>= 1) s += __shfl_xor_sync(0xffffffffu, s, o);
            if (lane == 0) {
                float c = s + bias[col];
                float r = fminf(8.f, fmaxf(-8.f, rintf(c * 2.f)));
                C[(size_t)row * D_MODEL + col] = __float2half(r * 0.5f);
            }
        }
    }
}

// ---------------------------------------------------------------------------
// Flash attention: pure fp16 mma (1 product QK^T and PV), fused qk-norm.
// ---------------------------------------------------------------------------
#define AT_ROWB 144
#define FA_SMEM (128 * AT_ROWB)   /* 18432 */

__global__ __launch_bounds__(256, 1) void flash_mma(
    const __half* __restrict__ Qg, const __half* __restrict__ Kg,
    const __half* __restrict__ Vg,
    const float* __restrict__ gq, const float* __restrict__ gk,
    __half* __restrict__ Og)
{
    extern __shared__ char smp[];
    const uint32_t sb = smem_u32(smp);
    const int oQ = 0, oK = 0, oV = 64 * AT_ROWB;

    const int tid = threadIdx.x, wid = tid >> 5, lane = tid & 31;
    const int b = blockIdx.y >> 4, h = blockIdx.y & 15;
    const int q0 = blockIdx.x * 128;

    const int lr = lane & 7, l3 = (lane >> 3) & 1, l4 = (lane >> 4) & 1;

    {
        const int row = tid >> 1;
        const int cb = (tid & 1) * 32;
        const __half* qp = Qg + ((size_t)(b * SEQ + q0 + row)) * D_MODEL + h * HEAD_DIM + cb;
        float v[32];
        const uint4* qp4 = (const uint4*)qp;
#pragma unroll
        for (int u = 0; u < 4; u++) {
            uint4 raw = qp4[u];
            const __half2* hp = (const __half2*)&raw;
#pragma unroll
            for (int j = 0; j < 4; j++) {
                float2 f = __half22float2(hp[j]);
                v[u * 8 + j * 2] = f.x;  v[u * 8 + j * 2 + 1] = f.y;
            }
        }
        float ss = 0.f;
#pragma unroll
        for (int i = 0; i < 32; i++) ss = fmaf(v[i], v[i], ss);
        ss += __shfl_xor_sync(0xffffffffu, ss, 1);
        const float inv = rsqrtf(ss * (1.0f / 64.0f) + 1e-6f) * 0.125f;

        char* dq = smp + oQ + row * AT_ROWB + cb * 2;
#pragma unroll
        for (int t = 0; t < 16; t++) {
            float a = v[t * 2]     * inv * __ldg(gq + cb + t * 2);
            float c = v[t * 2 + 1] * inv * __ldg(gq + cb + t * 2 + 1);
            *(__half2*)(dq + t * 4) = __floats2half2_rn(a, c);
        }
    }
    __syncthreads();

    uint32_t qf[4][4];
    {
        const int rbase = wid * 16 + lr + l3 * 8;
#pragma unroll
        for (int ks = 0; ks < 4; ks++)
            ldm_x4(qf[ks][0], qf[ks][1], qf[ks][2], qf[ks][3],
                   sb + oQ + rbase * AT_ROWB + ks * 32 + l4 * 16);
    }
    __syncthreads();

    float m_lo = -INFINITY, m_hi = -INFINITY, l_lo = 0.f, l_hi = 0.f;
    float acc[8][4];
#pragma unroll
    for (int i = 0; i < 8; i++)
#pragma unroll
        for (int j = 0; j < 4; j++) acc[i][j] = 0.f;

    for (int kt = 0; kt < SEQ / 64; kt++) {
        {
            const int row = tid >> 2;
            const int cb = (tid & 3) * 16;
            const __half* kp = Kg + ((size_t)(b * SEQ + kt * 64 + row)) * D_MODEL + h * HEAD_DIM + cb;
            const __half* vp = Vg + ((size_t)(b * SEQ + kt * 64 + row)) * D_MODEL + h * HEAD_DIM + cb;
            float kv[16];
            const uint4* kp4 = (const uint4*)kp;
            const uint4* vp4 = (const uint4*)vp;
            char* dk = smp + oK + row * AT_ROWB + cb * 2;
            char* dv = smp + oV + row * AT_ROWB + cb * 2;
#pragma unroll
            for (int u = 0; u < 2; u++) {
                uint4 kr = kp4[u];
                *(uint4*)(dv + u * 16) = vp4[u];
                const __half2* khp = (const __half2*)&kr;
#pragma unroll
                for (int j = 0; j < 4; j++) {
                    float2 kf = __half22float2(khp[j]);
                    kv[u * 8 + j * 2] = kf.x;  kv[u * 8 + j * 2 + 1] = kf.y;
                }
            }
            float ss = 0.f;
#pragma unroll
            for (int i = 0; i < 16; i++) ss = fmaf(kv[i], kv[i], ss);
            ss += __shfl_xor_sync(0xffffffffu, ss, 1);
            ss += __shfl_xor_sync(0xffffffffu, ss, 2);
            const float inv = rsqrtf(ss * (1.0f / 64.0f) + 1e-6f);
#pragma unroll
            for (int t = 0; t < 8; t++) {
                float a = kv[t * 2]     * inv * __ldg(gk + cb + t * 2);
                float c = kv[t * 2 + 1] * inv * __ldg(gk + cb + t * 2 + 1);
                *(__half2*)(dk + t * 4) = __floats2half2_rn(a, c);
            }
        }
        __syncthreads();

        float s[8][4];
#pragma unroll
        for (int i = 0; i < 8; i++)
#pragma unroll
            for (int j = 0; j < 4; j++) s[i][j] = 0.f;

#pragma unroll
        for (int np = 0; np < 4; np++) {
            const int rb = np * 16 + lr + l4 * 8;
#pragma unroll
            for (int ks = 0; ks < 4; ks++) {
                uint32_t k0, k1, k2, k3;
                ldm_x4(k0, k1, k2, k3, sb + oK + rb * AT_ROWB + ks * 32 + l3 * 16);
                uint32_t b0[2] = {k0, k1}, b1[2] = {k2, k3};
                mma_f16(s[np * 2 + 0], qf[ks], b0);
                mma_f16(s[np * 2 + 1], qf[ks], b1);
            }
        }

        float mx_lo = m_lo, mx_hi = m_hi;
#pragma unroll
        for (int i = 0; i < 8; i++) {
            mx_lo = fmaxf(mx_lo, fmaxf(s[i][0], s[i][1]));
            mx_hi = fmaxf(mx_hi, fmaxf(s[i][2], s[i][3]));
        }
        mx_lo = fmaxf(mx_lo, __shfl_xor_sync(0xffffffffu, mx_lo, 1));
        mx_lo = fmaxf(mx_lo, __shfl_xor_sync(0xffffffffu, mx_lo, 2));
        mx_hi = fmaxf(mx_hi, __shfl_xor_sync(0xffffffffu, mx_hi, 1));
        mx_hi = fmaxf(mx_hi, __shfl_xor_sync(0xffffffffu, mx_hi, 2));

        const float corr_lo = __expf(m_lo - mx_lo);
        const float corr_hi = __expf(m_hi - mx_hi);
        m_lo = mx_lo; m_hi = mx_hi;
        l_lo *= corr_lo; l_hi *= corr_hi;
#pragma unroll
        for (int i = 0; i < 8; i++) {
            acc[i][0] *= corr_lo; acc[i][1] *= corr_lo;
            acc[i][2] *= corr_hi; acc[i][3] *= corr_hi;
        }

        uint32_t ph[4][4];
#pragma unroll
        for (int t = 0; t < 4; t++) {
#pragma unroll
            for (int half_ = 0; half_ < 2; half_++) {
                const int nt = 2 * t + half_;
                float p0 = __expf(s[nt][0] - mx_lo);
                float p1 = __expf(s[nt][1] - mx_lo);
                float p2 = __expf(s[nt][2] - mx_hi);
                float p3 = __expf(s[nt][3] - mx_hi);
                l_lo += p0 + p1; l_hi += p2 + p3;
                __half2 h01 = __floats2half2_rn(p0, p1);
                __half2 h23 = __floats2half2_rn(p2, p3);
                ph[t][half_ * 2 + 0] = *(uint32_t*)&h01;
                ph[t][half_ * 2 + 1] = *(uint32_t*)&h23;
            }
        }

#pragma unroll
        for (int np = 0; np < 4; np++) {
#pragma unroll
            for (int t = 0; t < 4; t++) {
                uint32_t v0, v1, v2, v3;
                ldm_x4t(v0, v1, v2, v3,
                        sb + oV + (t * 16 + lr + l3 * 8) * AT_ROWB + np * 32 + l4 * 16);
                uint32_t b0[2] = {v0, v1}, b1[2] = {v2, v3};
                mma_f16(acc[np * 2 + 0], ph[t], b0);
                mma_f16(acc[np * 2 + 1], ph[t], b1);
            }
        }
        __syncthreads();
    }

    l_lo += __shfl_xor_sync(0xffffffffu, l_lo, 1);
    l_lo += __shfl_xor_sync(0xffffffffu, l_lo, 2);
    l_hi += __shfl_xor_sync(0xffffffffu, l_hi, 1);
    l_hi += __shfl_xor_sync(0xffffffffu, l_hi, 2);
    const float inv_lo = 1.0f / l_lo;
    const float inv_hi = 1.0f / l_hi;

    const int r_lo = q0 + wid * 16 + (lane >> 2);
    const int r_hi = r_lo + 8;
    const size_t base_lo = ((size_t)(b * SEQ + r_lo)) * D_MODEL + h * HEAD_DIM + (lane & 3) * 2;
    const size_t base_hi = ((size_t)(b * SEQ + r_hi)) * D_MODEL + h * HEAD_DIM + (lane & 3) * 2;
#pragma unroll
    for (int nt = 0; nt < 8; nt++) {
        *(__half2*)(Og + base_lo + nt * 8) = __floats2half2_rn(acc[nt][0] * inv_lo, acc[nt][1] * inv_lo);
        *(__half2*)(Og + base_hi + nt * 8) = __floats2half2_rn(acc[nt][2] * inv_hi, acc[nt][3] * inv_hi);
    }
}

// ---------------------------------------------------------------------------
// Wo GEMM: plain fp16 mma (1 product), fp32 bias + output.
// ---------------------------------------------------------------------------
__global__ __launch_bounds__(256, 2) void gemm_out(
    const __half* __restrict__ Ah, const __half* __restrict__ Wh,
    const float* __restrict__ bias, float* __restrict__ C)
{
    extern __shared__ char dsm[];
    const uint32_t sb = smem_u32(dsm);

    const int tid = threadIdx.x;
    const int wid = tid >> 5;
    const int lane = tid & 31;
    const int wm = wid >> 2;
    const int wn = wid & 3;
    const int bm = blockIdx.y * BM;
    const int bn = blockIdx.x * BN;

    const __half* mats[2] = {Ah, Wh};

    auto load_stage = [&](int sg, int kt) {
        const int kbase = kt * BK;
#pragma unroll
        for (int i = 0; i < 4; i++) {
            int idx = tid + i * 256;
            int mat = idx >> 9;
            int w = idx & 511;
            int row = w >> 2;
            int c = w & 3;
            int grow = (mat ? bn : bm) + row;
            const __half* gp = mats[mat] + (size_t)grow * D_MODEL + kbase + c * 8;
            uint32_t sa = sb + sg * HSTAGEB + mat * HMATB + row * ROWB + c * 16;
            cp_async16(sa, gp);
        }
    };

    float acc[4][4][4];
#pragma unroll
    for (int a = 0; a < 4; a++)
#pragma unroll
        for (int b2 = 0; b2 < 4; b2++)
#pragma unroll
            for (int q = 0; q < 4; q++) acc[a][b2][q] = 0.f;

    load_stage(0, 0); CP_COMMIT();
    load_stage(1, 1); CP_COMMIT();

    const int lr = lane & 7;
    const int l3 = (lane >> 3) & 1;
    const int l4 = (lane >> 4) & 1;

    const int NK = D_MODEL / BK;
    for (int kt = 0; kt < NK; kt++) {
        const int sg = kt & 1;
        CP_WAIT1();
        __syncthreads();

        const uint32_t abase = sb + sg * HSTAGEB + (wm * 64) * ROWB;
        const uint32_t wbase = sb + sg * HSTAGEB + HMATB + (wn * 32) * ROWB;

#pragma unroll
        for (int ks = 0; ks < 2; ks++) {
            uint32_t af[4][4];
            uint32_t bf_[4][2];
#pragma unroll
            for (int mt = 0; mt < 4; mt++) {
                uint32_t addr = abase + (mt * 16 + lr + l3 * 8) * ROWB + ks * 32 + l4 * 16;
                ldm_x4(af[mt][0], af[mt][1], af[mt][2], af[mt][3], addr);
            }
#pragma unroll
            for (int pr = 0; pr < 2; pr++) {
                uint32_t r0, r1, r2, r3;
                uint32_t addr = wbase + (pr * 16 + lr + l4 * 8) * ROWB + ks * 32 + l3 * 16;
                ldm_x4(r0, r1, r2, r3, addr);
                bf_[pr * 2 + 0][0] = r0;  bf_[pr * 2 + 0][1] = r1;
                bf_[pr * 2 + 1][0] = r2;  bf_[pr * 2 + 1][1] = r3;
            }
#pragma unroll
            for (int mt = 0; mt < 4; mt++)
#pragma unroll
                for (int nt = 0; nt < 4; nt++)
                    mma_f16(acc[mt][nt], af[mt], bf_[nt]);
        }
        __syncthreads();
        if (kt + 2 < NK) load_stage(sg, kt + 2);
        CP_COMMIT();
    }

    const int qrow = lane >> 2;
    const int qcol = (lane & 3) * 2;
#pragma unroll
    for (int mt = 0; mt < 4; mt++) {
#pragma unroll
        for (int nt = 0; nt < 4; nt++) {
            const int col = bn + wn * 32 + nt * 8 + qcol;
            const float b0 = bias[col], b1 = bias[col + 1];
#pragma unroll
            for (int half_ = 0; half_ < 2; half_++) {
                const int row = bm + wm * 64 + mt * 16 + qrow + half_ * 8;
                float v0 = acc[mt][nt][half_ * 2 + 0] + b0;
                float v1 = acc[mt][nt][half_ * 2 + 1] + b1;
                *(float2*)(C + (size_t)row * D_MODEL + col) = make_float2(v0, v1);
            }
        }
    }
}

// ---------------------------------------------------------------------------
// Launcher
// ---------------------------------------------------------------------------
extern "C" void kernel_launch(void* const* d_in, const int* in_sizes, int n_in,
                              void* d_out, int out_size)
{
    (void)in_sizes; (void)n_in; (void)out_size;
    const float* x  = (const float*)d_in[0];
    const float* Wq = (const float*)d_in[1];
    const float* bq = (const float*)d_in[2];
    const float* Wk = (const float*)d_in[3];
    const float* bk = (const float*)d_in[4];
    const float* Wv = (const float*)d_in[5];
    const float* bv = (const float*)d_in[6];
    const float* Wo = (const float*)d_in[7];
    const float* bo = (const float*)d_in[8];
    const float* gq = (const float*)d_in[9];
    const float* gk = (const float*)d_in[10];
    float* out = (float*)d_out;

    __half *xhlf, *whlf, *wo, *qh, *kh, *vh, *aat;
    uint32_t* bits;
    cudaGetSymbolAddress((void**)&xhlf, g_xhlf);
    cudaGetSymbolAddress((void**)&whlf, g_whlf);
    cudaGetSymbolAddress((void**)&wo, g_wo);
    cudaGetSymbolAddress((void**)&qh, g_qh);
    cudaGetSymbolAddress((void**)&kh, g_kh);
    cudaGetSymbolAddress((void**)&vh, g_vh);
    cudaGetSymbolAddress((void**)&aat, g_aat);
    cudaGetSymbolAddress((void**)&bits, g_flagbits);

    cudaFuncSetAttribute(gemm_hsfn, cudaFuncAttributeMaxDynamicSharedMemorySize, HGEMM_SMEM);
    cudaFuncSetAttribute(gemm_out, cudaFuncAttributeMaxDynamicSharedMemorySize, HGEMM_SMEM);
    cudaFuncSetAttribute(flash_mma, cudaFuncAttributeMaxDynamicSharedMemorySize, FA_SMEM);

    const int nx4 = MTOT * D_MODEL / 4;
    const int nw4 = DD / 4;
    const int ntot = nx4 + 4 * nw4;

    conv_all<<<(ntot + 255) / 256, 256>>>((const float4*)x, (const float4*)Wq,
                                          (const float4*)Wk, (const float4*)Wv,
                                          (const float4*)Wo, (uint2*)xhlf,
                                          (uint2*)whlf, (uint2*)wo, nx4, nw4);
    zero_bits<<<(NBITS_WORDS + 255) / 256, 256>>>(bits);

    {
        dim3 ggrid(D_MODEL / BN, MTOT / BM, 3);
        gemm_hsfn<<<ggrid, 256, HGEMM_SMEM>>>(xhlf, whlf, bq, bk, bv, qh, kh, vh, bits);
    }

    fixup_kernel<<<4096, 256>>>(x, Wq, Wk, Wv, bq, bk, bv, qh, kh, vh, bits);

    {
        dim3 fgrid(SEQ / 128, BATCH * NHEAD);
        flash_mma<<<fgrid, 256, FA_SMEM>>>(qh, kh, vh, gq, gk, aat);
    }

    {
        dim3 mgrid(D_MODEL / BN, MTOT / BM);
        gemm_out<<<mgrid, 256, HGEMM_SMEM>>>(aat, wo, bo, out);
    }
}